// round 1
// baseline (speedup 1.0000x reference)
#include <cuda_runtime.h>
#include <cuda_bf16.h>
#include <math.h>

// ---------------------------------------------------------------------------
// Problem constants
// ---------------------------------------------------------------------------
#define BB 4
#define NTOK 3136          // 56*56
#define NC 1568            // 2*28*28
#define DD 384
#define NH 12
#define DH 32
#define BH (BB*NH)         // 48
#define D2 768
#define NP 784             // 28*28
#define SCALE 0.17677669529663687f   // 32^-0.5
#define Y_ELEMS (BB*NP*D2)           // 2408448

// ---------------------------------------------------------------------------
// Scratch (device globals; no allocation allowed)
// ---------------------------------------------------------------------------
__device__ float g_xn[BB*NTOK*DD];
__device__ float g_cn[BB*NC*DD];
__device__ float g_q [BH*NC*DH];
__device__ float g_k [BH*NTOK*DH];
__device__ float g_v [BH*NTOK*DH];
__device__ float g_m [BH*NTOK];
__device__ float g_z [BH*NTOK];
__device__ float g_c2[BB*NC*DD];
__device__ float g_ts[BH*NC];
__device__ float g_y1[BB*NC*DD];
__device__ float g_yn2[BB*NP*D2];

// ---------------------------------------------------------------------------
// LayerNorm: one CTA (128 threads) per row of width D (384 or 768)
// ---------------------------------------------------------------------------
template<int D>
__global__ void ln_kernel(const float* __restrict__ in, const float* __restrict__ gamma,
                          float* __restrict__ out)
{
    constexpr int PT = D / 128;
    __shared__ float red[4];
    const int row = blockIdx.x;
    const int tid = threadIdx.x;
    const float* p = in + (size_t)row * D;

    float v[PT];
#pragma unroll
    for (int i = 0; i < PT; i++) v[i] = p[tid + i * 128];

    float s = 0.f;
#pragma unroll
    for (int i = 0; i < PT; i++) s += v[i];
#pragma unroll
    for (int o = 16; o > 0; o >>= 1) s += __shfl_xor_sync(0xffffffffu, s, o);
    if ((tid & 31) == 0) red[tid >> 5] = s;
    __syncthreads();
    const float mu = (red[0] + red[1] + red[2] + red[3]) * (1.0f / D);
    __syncthreads();

    float s2 = 0.f;
#pragma unroll
    for (int i = 0; i < PT; i++) { float dv = v[i] - mu; s2 += dv * dv; }
#pragma unroll
    for (int o = 16; o > 0; o >>= 1) s2 += __shfl_xor_sync(0xffffffffu, s2, o);
    if ((tid & 31) == 0) red[tid >> 5] = s2;
    __syncthreads();
    const float var = (red[0] + red[1] + red[2] + red[3]) * (1.0f / D);
    const float rs = rsqrtf(var + 1e-6f);

    float* po = out + (size_t)row * D;
#pragma unroll
    for (int i = 0; i < PT; i++)
        po[tid + i * 128] = (v[i] - mu) * rs * gamma[tid + i * 128];
}

// ---------------------------------------------------------------------------
// Generic fp32 SGEMM, 128x128 tile, 8x8 per-thread, BK=8, 256 threads.
// mode 0: C0[row*N+col] = acc                               (plain)
// mode 1: Q scatter    -> g_q  [((b*12+h)*NC + c)*32 + t]
// mode 2: KV scatter   -> g_k/g_v [((b*12+h)*NTOK + nn)*32 + t]
// mode 3: residual     -> C0 = acc + aux1[row,col]*aux2[col]
// ---------------------------------------------------------------------------
__global__ void sgemm_k(const float* __restrict__ A, const float* __restrict__ B,
                        float* __restrict__ C0, float* __restrict__ C1,
                        int M, int N, int K, int mode,
                        const float* __restrict__ aux1, const float* __restrict__ aux2)
{
    __shared__ float As[8][128];
    __shared__ float Bs[8][128];
    const int tid  = threadIdx.x;
    const int brow = blockIdx.y * 128;
    const int bcol = blockIdx.x * 128;
    const int a_r  = tid >> 1;
    const int a_c  = (tid & 1) << 2;
    const int b_r  = tid >> 5;
    const int b_c  = (tid & 31) << 2;
    const int tx   = tid & 15, ty = tid >> 4;

    float acc[8][8];
#pragma unroll
    for (int i = 0; i < 8; i++)
#pragma unroll
        for (int j = 0; j < 8; j++) acc[i][j] = 0.f;

    const int arow = brow + a_r;
    const bool aval = arow < M;

    for (int k0 = 0; k0 < K; k0 += 8) {
        float4 av = make_float4(0.f, 0.f, 0.f, 0.f);
        if (aval) av = *(const float4*)(A + (size_t)arow * K + k0 + a_c);
        As[a_c + 0][a_r] = av.x; As[a_c + 1][a_r] = av.y;
        As[a_c + 2][a_r] = av.z; As[a_c + 3][a_r] = av.w;
        float4 bv = *(const float4*)(B + (size_t)(k0 + b_r) * N + bcol + b_c);
        *(float4*)&Bs[b_r][b_c] = bv;
        __syncthreads();
#pragma unroll
        for (int kk = 0; kk < 8; kk++) {
            float4 a0 = *(float4*)&As[kk][ty * 8];
            float4 a1 = *(float4*)&As[kk][ty * 8 + 4];
            float4 b0 = *(float4*)&Bs[kk][tx * 8];
            float4 b1 = *(float4*)&Bs[kk][tx * 8 + 4];
            float a[8] = {a0.x, a0.y, a0.z, a0.w, a1.x, a1.y, a1.z, a1.w};
            float b[8] = {b0.x, b0.y, b0.z, b0.w, b1.x, b1.y, b1.z, b1.w};
#pragma unroll
            for (int i = 0; i < 8; i++)
#pragma unroll
                for (int j = 0; j < 8; j++)
                    acc[i][j] = fmaf(a[i], b[j], acc[i][j]);
        }
        __syncthreads();
    }

#pragma unroll
    for (int i = 0; i < 8; i++) {
        const int row = brow + ty * 8 + i;
        if (row >= M) continue;
#pragma unroll
        for (int j = 0; j < 8; j++) {
            const int col = bcol + tx * 8 + j;
            const float v = acc[i][j];
            if (mode == 0) {
                C0[(size_t)row * N + col] = v;
            } else if (mode == 1) {
                const int b = row / NC, c = row % NC;
                const int h = col >> 5, t = col & 31;
                C0[(((size_t)(b * NH + h)) * NC + c) * DH + t] = v;
            } else if (mode == 2) {
                const int b = row / NTOK, nn = row % NTOK;
                const int kvi = col / DD, r = col % DD;
                const int h = r >> 5, t = r & 31;
                float* dst = kvi ? C1 : C0;
                dst[(((size_t)(b * NH + h)) * NTOK + nn) * DH + t] = v;
            } else { // mode 3
                C0[(size_t)row * N + col] =
                    v + aux1[(size_t)row * N + col] * aux2[col];
            }
        }
    }
}

// ---------------------------------------------------------------------------
// Pass 1: per (b,h), online row-softmax stats over clusters.
// Token tile 64, cluster chunks of 128 (13 chunks, last masked).
// Thread layout: 16x16; thread covers 4 tokens x 8 clusters.
// ---------------------------------------------------------------------------
__global__ void pass1_kernel()
{
    const int bh   = blockIdx.y;
    const int tok0 = blockIdx.x * 64;
    __shared__ float Ks[32][64];
    __shared__ float Qs[32][128];
    const int tid = threadIdx.x;
    const int tx  = tid & 15, ty = tid >> 4;

    { // load K tile (64 tok x 32), transposed
        const float* kp = g_k + ((size_t)bh * NTOK + tok0) * DH;
#pragma unroll
        for (int ii = 0; ii < 2; ii++) {
            const int f4 = tid * 2 + ii;
            const int tok = f4 >> 3;
            const int t = (f4 & 7) << 2;
            float4 v = *(const float4*)(kp + tok * DH + t);
            Ks[t + 0][tok] = v.x; Ks[t + 1][tok] = v.y;
            Ks[t + 2][tok] = v.z; Ks[t + 3][tok] = v.w;
        }
    }

    float m[4], z[4];
#pragma unroll
    for (int i = 0; i < 4; i++) { m[i] = -INFINITY; z[i] = 0.f; }

    const float* qp = g_q + (size_t)bh * NC * DH;
    for (int cc = 0; cc < 13; cc++) {
        const int c0 = cc * 128;
        __syncthreads();
#pragma unroll
        for (int ii = 0; ii < 4; ii++) {       // load Q chunk (128 c x 32), transposed
            const int f4 = tid * 4 + ii;
            const int cl = f4 >> 3;
            const int t  = (f4 & 7) << 2;
            const int c  = c0 + cl;
            float4 v = (c < NC) ? *(const float4*)(qp + (size_t)c * DH + t)
                                : make_float4(0.f, 0.f, 0.f, 0.f);
            Qs[t + 0][cl] = v.x; Qs[t + 1][cl] = v.y;
            Qs[t + 2][cl] = v.z; Qs[t + 3][cl] = v.w;
        }
        __syncthreads();

        float s[4][8];
#pragma unroll
        for (int i = 0; i < 4; i++)
#pragma unroll
            for (int j = 0; j < 8; j++) s[i][j] = 0.f;
#pragma unroll
        for (int t = 0; t < 32; t++) {
            float4 a  = *(float4*)&Ks[t][ty * 4];
            float4 b0 = *(float4*)&Qs[t][tx * 8];
            float4 b1 = *(float4*)&Qs[t][tx * 8 + 4];
            float aa[4] = {a.x, a.y, a.z, a.w};
            float bb[8] = {b0.x, b0.y, b0.z, b0.w, b1.x, b1.y, b1.z, b1.w};
#pragma unroll
            for (int i = 0; i < 4; i++)
#pragma unroll
                for (int j = 0; j < 8; j++)
                    s[i][j] = fmaf(aa[i], bb[j], s[i][j]);
        }

        const bool partial = (cc == 12);
#pragma unroll
        for (int i = 0; i < 4; i++) {
            float lm = -INFINITY;
#pragma unroll
            for (int j = 0; j < 8; j++) {
                float val = s[i][j] * SCALE;
                if (partial && (c0 + tx * 8 + j) >= NC) val = -INFINITY;
                s[i][j] = val;
                lm = fmaxf(lm, val);
            }
#pragma unroll
            for (int o = 1; o < 16; o <<= 1)
                lm = fmaxf(lm, __shfl_xor_sync(0xffffffffu, lm, o));
            const float nm = fmaxf(m[i], lm);
            float se = 0.f;
#pragma unroll
            for (int j = 0; j < 8; j++) se += __expf(s[i][j] - nm);
#pragma unroll
            for (int o = 1; o < 16; o <<= 1)
                se += __shfl_xor_sync(0xffffffffu, se, o);
            z[i] = z[i] * __expf(m[i] - nm) + se;
            m[i] = nm;
        }
    }

    if (tx == 0) {
#pragma unroll
        for (int i = 0; i < 4; i++) {
            const int tok = tok0 + ty * 4 + i;
            g_m[(size_t)bh * NTOK + tok] = m[i];
            g_z[(size_t)bh * NTOK + tok] = z[i];
        }
    }
}

// ---------------------------------------------------------------------------
// Pass 2: per (b,h,cluster-tile-128): recompute logits, form P in SMEM,
// accumulate c2 = P^T V (normalized in epilogue) + column sums ts.
// Token chunk 64 (3136 = 49*64, no tail). Dynamic smem ~66 KB.
// ---------------------------------------------------------------------------
#define PASS2_SMEM ((32*128 + 32*64 + 64*32 + 64*128 + 128) * 4)

__global__ void pass2_kernel()
{
    extern __shared__ float sm[];
    float* Qs    = sm;               // [32][128] transposed
    float* Ks    = Qs + 32 * 128;    // [32][64]  transposed
    float* Vs    = Ks + 32 * 64;     // [64][32]  row-major
    float* P     = Vs + 64 * 32;     // [64][128]
    float* sm_ts = P  + 64 * 128;    // [128]

    const int bh = blockIdx.y;
    const int b  = bh / NH, h = bh % NH;
    const int c0 = blockIdx.x * 128;
    const int tid = threadIdx.x;
    const int tx = tid & 15, ty = tid >> 4;
    const int cg = tid >> 3, tg = tid & 7;     // step-2 layout: 4 clusters x 4 dh

    { // load Q tile once (128 c x 32, transposed)
        const float* qp = g_q + (size_t)bh * NC * DH;
#pragma unroll
        for (int ii = 0; ii < 4; ii++) {
            const int f4 = tid * 4 + ii;
            const int cl = f4 >> 3;
            const int t  = (f4 & 7) << 2;
            const int c  = c0 + cl;
            float4 v = (c < NC) ? *(const float4*)(qp + (size_t)c * DH + t)
                                : make_float4(0.f, 0.f, 0.f, 0.f);
            Qs[(t + 0) * 128 + cl] = v.x; Qs[(t + 1) * 128 + cl] = v.y;
            Qs[(t + 2) * 128 + cl] = v.z; Qs[(t + 3) * 128 + cl] = v.w;
        }
    }

    float acc[4][4];
#pragma unroll
    for (int i = 0; i < 4; i++)
#pragma unroll
        for (int j = 0; j < 4; j++) acc[i][j] = 0.f;
    float ts[4] = {0.f, 0.f, 0.f, 0.f};

    for (int ch = 0; ch < 49; ch++) {
        const int tok0 = ch * 64;
        __syncthreads();   // prev step2 done; Qs visible on first iter
        { // load K chunk transposed + V chunk straight
            const float* kp = g_k + ((size_t)bh * NTOK + tok0) * DH;
#pragma unroll
            for (int ii = 0; ii < 2; ii++) {
                const int f4 = tid * 2 + ii;
                const int tok = f4 >> 3;
                const int t = (f4 & 7) << 2;
                float4 v = *(const float4*)(kp + tok * DH + t);
                Ks[(t + 0) * 64 + tok] = v.x; Ks[(t + 1) * 64 + tok] = v.y;
                Ks[(t + 2) * 64 + tok] = v.z; Ks[(t + 3) * 64 + tok] = v.w;
            }
            const float4* vp = (const float4*)(g_v + ((size_t)bh * NTOK + tok0) * DH);
#pragma unroll
            for (int ii = 0; ii < 2; ii++)
                ((float4*)Vs)[tid * 2 + ii] = vp[tid * 2 + ii];
        }
        __syncthreads();

        // step 1: logits + P
        float s[4][8];
#pragma unroll
        for (int i = 0; i < 4; i++)
#pragma unroll
            for (int j = 0; j < 8; j++) s[i][j] = 0.f;
#pragma unroll
        for (int t = 0; t < 32; t++) {
            float4 a  = *(float4*)&Ks[t * 64 + ty * 4];
            float4 b0 = *(float4*)&Qs[t * 128 + tx * 8];
            float4 b1 = *(float4*)&Qs[t * 128 + tx * 8 + 4];
            float aa[4] = {a.x, a.y, a.z, a.w};
            float bb[8] = {b0.x, b0.y, b0.z, b0.w, b1.x, b1.y, b1.z, b1.w};
#pragma unroll
            for (int i = 0; i < 4; i++)
#pragma unroll
                for (int j = 0; j < 8; j++)
                    s[i][j] = fmaf(aa[i], bb[j], s[i][j]);
        }
#pragma unroll
        for (int i = 0; i < 4; i++) {
            const int gt = tok0 + ty * 4 + i;
            const float mm = __ldg(&g_m[(size_t)bh * NTOK + gt]);
            const float rz = __fdividef(1.f, __ldg(&g_z[(size_t)bh * NTOK + gt]));
            float pr[8];
#pragma unroll
            for (int j = 0; j < 8; j++)
                pr[j] = __expf(s[i][j] * SCALE - mm) * rz;
            *(float4*)&P[(ty * 4 + i) * 128 + tx * 8]     = make_float4(pr[0], pr[1], pr[2], pr[3]);
            *(float4*)&P[(ty * 4 + i) * 128 + tx * 8 + 4] = make_float4(pr[4], pr[5], pr[6], pr[7]);
        }
        __syncthreads();

        // step 2: acc[c][t] += P^T V ; ts[c] += colsum(P)
#pragma unroll 4
        for (int tok = 0; tok < 64; tok++) {
            float4 pv = *(float4*)&P[tok * 128 + cg * 4];
            float4 vv = *(float4*)&Vs[tok * 32 + tg * 4];
            float pa[4] = {pv.x, pv.y, pv.z, pv.w};
            float va[4] = {vv.x, vv.y, vv.z, vv.w};
#pragma unroll
            for (int i = 0; i < 4; i++)
#pragma unroll
                for (int j = 0; j < 4; j++)
                    acc[i][j] = fmaf(pa[i], va[j], acc[i][j]);
            if (tg == 0) {
#pragma unroll
                for (int i = 0; i < 4; i++) ts[i] += pa[i];
            }
        }
    }

    __syncthreads();
    if (tg == 0) {
#pragma unroll
        for (int i = 0; i < 4; i++) sm_ts[cg * 4 + i] = ts[i];
    }
    __syncthreads();

#pragma unroll
    for (int i = 0; i < 4; i++) {
        const int c = c0 + cg * 4 + i;
        if (c >= NC) continue;
        const float tsv = sm_ts[cg * 4 + i];
        const float inv = __fdividef(1.f, tsv + 1e-6f);
#pragma unroll
        for (int j = 0; j < 4; j++)
            g_c2[((size_t)b * NC + c) * DD + h * DH + tg * 4 + j] = acc[i][j] * inv;
        if (tg == 0) g_ts[(size_t)bh * NC + c] = tsv;
    }
}

// ---------------------------------------------------------------------------
// token_sizes: mean over heads, then pair-sum -> [b, 784]
// ---------------------------------------------------------------------------
__global__ void ts_kernel(float* __restrict__ outp)
{
    const int idx = blockIdx.x * blockDim.x + threadIdx.x;
    if (idx >= BB * NP) return;
    const int b = idx / NP, pp = idx % NP;
    float s = 0.f;
#pragma unroll
    for (int h = 0; h < NH; h++) {
        const float* t = g_ts + ((size_t)(b * NH + h)) * NC + 2 * pp;
        s += t[0] + t[1];
    }
    outp[idx] = s * (1.0f / NH);
}

// ---------------------------------------------------------------------------
// Launch
// ---------------------------------------------------------------------------
extern "C" void kernel_launch(void* const* d_in, const int* in_sizes, int n_in,
                              void* d_out, int out_size)
{
    (void)in_sizes; (void)n_in; (void)out_size;
    const float* x         = (const float*)d_in[0];
    const float* clusters  = (const float*)d_in[1];
    const float* g1        = (const float*)d_in[2];
    const float* Wq        = (const float*)d_in[3];
    const float* Wkv       = (const float*)d_in[4];
    const float* Wo        = (const float*)d_in[5];
    const float* res_scale = (const float*)d_in[6];
    const float* g2        = (const float*)d_in[7];
    const float* Wproj     = (const float*)d_in[8];
    float* out = (float*)d_out;

    float *p_xn, *p_cn, *p_q, *p_k, *p_v, *p_c2, *p_y1, *p_yn2;
    cudaGetSymbolAddress((void**)&p_xn,  g_xn);
    cudaGetSymbolAddress((void**)&p_cn,  g_cn);
    cudaGetSymbolAddress((void**)&p_q,   g_q);
    cudaGetSymbolAddress((void**)&p_k,   g_k);
    cudaGetSymbolAddress((void**)&p_v,   g_v);
    cudaGetSymbolAddress((void**)&p_c2,  g_c2);
    cudaGetSymbolAddress((void**)&p_y1,  g_y1);
    cudaGetSymbolAddress((void**)&p_yn2, g_yn2);

    cudaFuncSetAttribute(pass2_kernel,
                         cudaFuncAttributeMaxDynamicSharedMemorySize, PASS2_SMEM);

    // 1) LayerNorms
    ln_kernel<DD><<<BB * NTOK, 128>>>(x, g1, p_xn);
    ln_kernel<DD><<<BB * NC, 128>>>(clusters, g1, p_cn);

    // 2) Projections (scatter into per-head layouts)
    sgemm_k<<<dim3(3, 49), 256>>>(p_cn, Wq, p_q, nullptr,
                                  BB * NC, DD, DD, 1, nullptr, nullptr);
    sgemm_k<<<dim3(6, 98), 256>>>(p_xn, Wkv, p_k, p_v,
                                  BB * NTOK, 2 * DD, DD, 2, nullptr, nullptr);

    // 3) Softmax stats (over cluster axis) + fused P^T V
    pass1_kernel<<<dim3(49, BH), 256>>>();
    pass2_kernel<<<dim3(13, BH), 256, PASS2_SMEM>>>();

    // 4) Wo + residual
    sgemm_k<<<dim3(3, 49), 256>>>(p_c2, Wo, p_y1, nullptr,
                                  BB * NC, DD, DD, 3, clusters, res_scale);

    // 5) LN2 over [b,784,768] + final projection straight into d_out
    ln_kernel<D2><<<BB * NP, 128>>>(p_y1, g2, p_yn2);
    sgemm_k<<<dim3(6, 25), 256>>>(p_yn2, Wproj, out, nullptr,
                                  BB * NP, D2, D2, 0, nullptr, nullptr);

    // 6) token_sizes tail
    ts_kernel<<<(BB * NP + 255) / 256, 256>>>(out + Y_ELEMS);
}

// round 3
// speedup vs baseline: 1.2398x; 1.2398x over previous
#include <cuda_runtime.h>
#include <cuda_bf16.h>
#include <mma.h>
#include <math.h>

using namespace nvcuda;

// ---------------------------------------------------------------------------
// Problem constants
// ---------------------------------------------------------------------------
#define BB 4
#define NTOK 3136          // 56*56
#define NC 1568            // 2*28*28
#define DD 384
#define NH 12
#define DH 32
#define BH (BB*NH)         // 48
#define D2 768
#define NP 784             // 28*28
#define SCALE 0.17677669529663687f   // 32^-0.5
#define Y_ELEMS (BB*NP*D2)           // 2408448

typedef wmma::fragment<wmma::matrix_a, 16, 16, 8, wmma::precision::tf32, wmma::row_major> FragA;
typedef wmma::fragment<wmma::matrix_b, 16, 16, 8, wmma::precision::tf32, wmma::row_major> FragB;
typedef wmma::fragment<wmma::accumulator, 16, 16, 8, float> FragC;

__device__ __forceinline__ float to_tf32(float x) { return wmma::__float_to_tf32(x); }

// ---------------------------------------------------------------------------
// Scratch (device globals; no allocation allowed)
// ---------------------------------------------------------------------------
__device__ float g_xn[BB*NTOK*DD];
__device__ float g_cn[BB*NC*DD];
__device__ float g_q [BH*NC*DH];
__device__ float g_k [BH*NTOK*DH];
__device__ float g_v [BH*NTOK*DH];
__device__ float g_w [BH*NTOK];          // exp(-m)/z per (b,h,token)
__device__ float g_c2[BB*NC*DD];
__device__ float g_ts[BH*NC];
__device__ float g_y1[BB*NC*DD];
__device__ float g_yn2[BB*NP*D2];

// ---------------------------------------------------------------------------
// LayerNorm: one CTA (128 threads) per row of width D (384 or 768)
// ---------------------------------------------------------------------------
template<int D>
__global__ void ln_kernel(const float* __restrict__ in, const float* __restrict__ gamma,
                          float* __restrict__ out)
{
    constexpr int PT = D / 128;
    __shared__ float red[4];
    const int row = blockIdx.x;
    const int tid = threadIdx.x;
    const float* p = in + (size_t)row * D;

    float v[PT];
#pragma unroll
    for (int i = 0; i < PT; i++) v[i] = p[tid + i * 128];

    float s = 0.f;
#pragma unroll
    for (int i = 0; i < PT; i++) s += v[i];
#pragma unroll
    for (int o = 16; o > 0; o >>= 1) s += __shfl_xor_sync(0xffffffffu, s, o);
    if ((tid & 31) == 0) red[tid >> 5] = s;
    __syncthreads();
    const float mu = (red[0] + red[1] + red[2] + red[3]) * (1.0f / D);
    __syncthreads();

    float s2 = 0.f;
#pragma unroll
    for (int i = 0; i < PT; i++) { float dv = v[i] - mu; s2 += dv * dv; }
#pragma unroll
    for (int o = 16; o > 0; o >>= 1) s2 += __shfl_xor_sync(0xffffffffu, s2, o);
    if ((tid & 31) == 0) red[tid >> 5] = s2;
    __syncthreads();
    const float var = (red[0] + red[1] + red[2] + red[3]) * (1.0f / D);
    const float rs = rsqrtf(var + 1e-6f);

    float* po = out + (size_t)row * D;
#pragma unroll
    for (int i = 0; i < PT; i++)
        po[tid + i * 128] = (v[i] - mu) * rs * gamma[tid + i * 128];
}

// ---------------------------------------------------------------------------
// TF32 WMMA GEMM, 128x128 tile, BK=32, 8 warps (256 thr), epilogue via SMEM.
// mode 0: plain C0[row*N+col]
// mode 1: Q scatter  -> g_q  [((b*12+h)*NC + c)*32 + t]
// mode 2: KV scatter -> g_k/g_v
// mode 3: residual   -> C0 = acc + aux1[row,col]*aux2[col]
// ---------------------------------------------------------------------------
#define GEMM_SMEM (128*132*4)

__global__ void sgemm_wmma(const float* __restrict__ A, const float* __restrict__ B,
                           float* __restrict__ C0, float* __restrict__ C1,
                           int M, int N, int K, int mode,
                           const float* __restrict__ aux1, const float* __restrict__ aux2)
{
    extern __shared__ float sm[];
    float* As = sm;               // [128][36]
    float* Bs = sm + 128 * 36;    // [32][132]
    float* Cs = sm;               // alias [128][132] (after mainloop)

    const int tid  = threadIdx.x;
    const int warp = tid >> 5;
    const int wm   = warp >> 2;   // 0..1 (64 rows each)
    const int wn   = warp & 3;    // 0..3 (32 cols each)
    const int brow = blockIdx.y * 128;
    const int bcol = blockIdx.x * 128;

    FragC acc[4][2];
#pragma unroll
    for (int i = 0; i < 4; i++)
#pragma unroll
        for (int j = 0; j < 2; j++) wmma::fill_fragment(acc[i][j], 0.f);

    for (int k0 = 0; k0 < K; k0 += 32) {
        // load A tile 128x32
#pragma unroll
        for (int ii = 0; ii < 4; ii++) {
            const int f = tid + ii * 256;
            const int r = f >> 3;
            const int c4 = (f & 7) << 2;
            const int gr = brow + r;
            float4 v = make_float4(0.f, 0.f, 0.f, 0.f);
            if (gr < M) v = *(const float4*)(A + (size_t)gr * K + k0 + c4);
            As[r * 36 + c4 + 0] = to_tf32(v.x); As[r * 36 + c4 + 1] = to_tf32(v.y);
            As[r * 36 + c4 + 2] = to_tf32(v.z); As[r * 36 + c4 + 3] = to_tf32(v.w);
        }
        // load B tile 32x128
#pragma unroll
        for (int ii = 0; ii < 4; ii++) {
            const int f = tid + ii * 256;
            const int kr = f >> 5;
            const int c4 = (f & 31) << 2;
            float4 v = *(const float4*)(B + (size_t)(k0 + kr) * N + bcol + c4);
            Bs[kr * 132 + c4 + 0] = to_tf32(v.x); Bs[kr * 132 + c4 + 1] = to_tf32(v.y);
            Bs[kr * 132 + c4 + 2] = to_tf32(v.z); Bs[kr * 132 + c4 + 3] = to_tf32(v.w);
        }
        __syncthreads();
#pragma unroll
        for (int kk = 0; kk < 32; kk += 8) {
            FragA a[4]; FragB b[2];
#pragma unroll
            for (int fm = 0; fm < 4; fm++)
                wmma::load_matrix_sync(a[fm], &As[(wm * 64 + fm * 16) * 36 + kk], 36);
#pragma unroll
            for (int fn = 0; fn < 2; fn++)
                wmma::load_matrix_sync(b[fn], &Bs[kk * 132 + wn * 32 + fn * 16], 132);
#pragma unroll
            for (int fm = 0; fm < 4; fm++)
#pragma unroll
                for (int fn = 0; fn < 2; fn++)
                    wmma::mma_sync(acc[fm][fn], a[fm], b[fn], acc[fm][fn]);
        }
        __syncthreads();
    }

    // epilogue via SMEM (aliases As/Bs)
#pragma unroll
    for (int fm = 0; fm < 4; fm++)
#pragma unroll
        for (int fn = 0; fn < 2; fn++)
            wmma::store_matrix_sync(&Cs[(wm * 64 + fm * 16) * 132 + wn * 32 + fn * 16],
                                    acc[fm][fn], 132, wmma::mem_row_major);
    __syncthreads();

#pragma unroll
    for (int j = 0; j < 64; j++) {
        const int e = tid + j * 256;
        const int r = e >> 7, c = e & 127;
        const int row = brow + r, col = bcol + c;
        if (row >= M) continue;
        const float v = Cs[r * 132 + c];
        if (mode == 0) {
            C0[(size_t)row * N + col] = v;
        } else if (mode == 1) {
            const int b = row / NC, cc = row % NC;
            const int h = col >> 5, t = col & 31;
            C0[(((size_t)(b * NH + h)) * NC + cc) * DH + t] = v;
        } else if (mode == 2) {
            const int b = row / NTOK, nn = row % NTOK;
            const int kvi = col / DD, rr = col % DD;
            const int h = rr >> 5, t = rr & 31;
            float* dst = kvi ? C1 : C0;
            dst[(((size_t)(b * NH + h)) * NTOK + nn) * DH + t] = v;
        } else { // mode 3
            C0[(size_t)row * N + col] = v + aux1[(size_t)row * N + col] * aux2[col];
        }
    }
}

// ---------------------------------------------------------------------------
// Pass 1: softmax-over-clusters stats. Per (b,h,tok-tile 64), 13 cluster
// chunks of 128. S = K·Qᵀ via wmma; online (m,z) -> g_w = exp(-m)/z.
// ---------------------------------------------------------------------------
#define P1_SMEM ((64*36 + 32*132 + 64*132) * 4)

__global__ void pass1_wmma()
{
    extern __shared__ float sm[];
    float* Ks = sm;               // [64 tok][36]   (tf32)
    float* Qt = Ks + 64 * 36;     // [32 dh][132 c] (tf32, transposed)
    float* Ss = Qt + 32 * 132;    // [64 tok][132 c]

    const int bh   = blockIdx.y;
    const int tok0 = blockIdx.x * 64;
    const int tid  = threadIdx.x;
    const int warp = tid >> 5;
    const int wm   = warp >> 2;   // 0..1 -> 32 tok rows
    const int wn   = warp & 3;    // 0..3 -> 32 cluster cols

    { // load K tile 64x32
        const float* kp = g_k + ((size_t)bh * NTOK + tok0) * DH;
#pragma unroll
        for (int ii = 0; ii < 2; ii++) {
            const int f = tid + ii * 256;
            const int tok = f >> 3, t4 = (f & 7) << 2;
            float4 v = *(const float4*)(kp + tok * DH + t4);
            Ks[tok * 36 + t4 + 0] = to_tf32(v.x); Ks[tok * 36 + t4 + 1] = to_tf32(v.y);
            Ks[tok * 36 + t4 + 2] = to_tf32(v.z); Ks[tok * 36 + t4 + 3] = to_tf32(v.w);
        }
    }

    const int myTok = tid >> 2;   // 64 tokens, 4 threads each
    const int q     = tid & 3;
    float m = -INFINITY, z = 0.f;

    const float* qp = g_q + (size_t)bh * NC * DH;
    for (int cc = 0; cc < 13; cc++) {
        const int c0 = cc * 128;
        __syncthreads();
        // load Q chunk 128x32 -> transposed Qt[dh][c]
#pragma unroll
        for (int ii = 0; ii < 4; ii++) {
            const int f = tid + ii * 256;
            const int c = f >> 3, t4 = (f & 7) << 2;
            const int gc = c0 + c;
            float4 v = make_float4(0.f, 0.f, 0.f, 0.f);
            if (gc < NC) v = *(const float4*)(qp + (size_t)gc * DH + t4);
            Qt[(t4 + 0) * 132 + c] = to_tf32(v.x); Qt[(t4 + 1) * 132 + c] = to_tf32(v.y);
            Qt[(t4 + 2) * 132 + c] = to_tf32(v.z); Qt[(t4 + 3) * 132 + c] = to_tf32(v.w);
        }
        __syncthreads();

        // S = K (64x32) x Q^T (32x128)
        FragC accS[2][2];
#pragma unroll
        for (int i = 0; i < 2; i++)
#pragma unroll
            for (int j = 0; j < 2; j++) wmma::fill_fragment(accS[i][j], 0.f);
#pragma unroll
        for (int kk = 0; kk < 32; kk += 8) {
            FragA a[2]; FragB b[2];
#pragma unroll
            for (int fm = 0; fm < 2; fm++)
                wmma::load_matrix_sync(a[fm], &Ks[(wm * 32 + fm * 16) * 36 + kk], 36);
#pragma unroll
            for (int fn = 0; fn < 2; fn++)
                wmma::load_matrix_sync(b[fn], &Qt[kk * 132 + wn * 32 + fn * 16], 132);
#pragma unroll
            for (int fm = 0; fm < 2; fm++)
#pragma unroll
                for (int fn = 0; fn < 2; fn++)
                    wmma::mma_sync(accS[fm][fn], a[fm], b[fn], accS[fm][fn]);
        }
#pragma unroll
        for (int fm = 0; fm < 2; fm++)
#pragma unroll
            for (int fn = 0; fn < 2; fn++)
                wmma::store_matrix_sync(&Ss[(wm * 32 + fm * 16) * 132 + wn * 32 + fn * 16],
                                        accS[fm][fn], 132, wmma::mem_row_major);
        __syncthreads();

        // online softmax update (each thread scans 32 clusters of its token)
        float lm = -INFINITY;
#pragma unroll
        for (int j = 0; j < 32; j++) {
            const int col = q * 32 + j;
            if (c0 + col < NC) lm = fmaxf(lm, Ss[myTok * 132 + col] * SCALE);
        }
        lm = fmaxf(lm, __shfl_xor_sync(0xffffffffu, lm, 1));
        lm = fmaxf(lm, __shfl_xor_sync(0xffffffffu, lm, 2));
        const float nm = fmaxf(m, lm);
        float se = 0.f;
#pragma unroll
        for (int j = 0; j < 32; j++) {
            const int col = q * 32 + j;
            if (c0 + col < NC) se += __expf(Ss[myTok * 132 + col] * SCALE - nm);
        }
        se += __shfl_xor_sync(0xffffffffu, se, 1);
        se += __shfl_xor_sync(0xffffffffu, se, 2);
        z = z * __expf(m - nm) + se;
        m = nm;
    }

    if (q == 0)
        g_w[(size_t)bh * NTOK + tok0 + myTok] = __fdividef(__expf(-m), z);
}

// ---------------------------------------------------------------------------
// Pass 2: per (b,h,cluster-tile 128): S = K·Qᵀ, P = exp(S·scale)·w (stored
// transposed), c2 += Pᵀ·V via wmma; ts = colsum(P). Normalize in epilogue.
// ---------------------------------------------------------------------------
#define P2_SMEM ((32*132 + 64*36 + 64*36 + 64*132 + 128*68 + 128 + 64) * 4)

__global__ void pass2_wmma()
{
    extern __shared__ float sm[];
    float* Qt   = sm;                 // [32][132]  (tf32, transposed)
    float* Ks   = Qt + 32 * 132;      // [64][36]
    float* Vs   = Ks + 64 * 36;       // [64][36]
    float* Ss   = Vs + 64 * 36;       // [64][132]
    float* Pt   = Ss + 64 * 132;      // [128 c][68 tok] (tf32, P transposed)
    float* ts_s = Pt + 128 * 68;      // [128]
    float* ws   = ts_s + 128;         // [64]
    float* Cs   = Ss;                 // alias [128][36] for epilogue

    const int bh = blockIdx.y;
    const int b  = bh / NH, h = bh % NH;
    const int c0 = blockIdx.x * 128;
    const int tid  = threadIdx.x;
    const int warp = tid >> 5;
    const int wm   = warp >> 2;
    const int wn   = warp & 3;

    { // load Q tile once (128c x 32dh) -> Qt[dh][c]
        const float* qp = g_q + (size_t)bh * NC * DH;
#pragma unroll
        for (int ii = 0; ii < 4; ii++) {
            const int f = tid + ii * 256;
            const int c = f >> 3, t4 = (f & 7) << 2;
            const int gc = c0 + c;
            float4 v = make_float4(0.f, 0.f, 0.f, 0.f);
            if (gc < NC) v = *(const float4*)(qp + (size_t)gc * DH + t4);
            Qt[(t4 + 0) * 132 + c] = to_tf32(v.x); Qt[(t4 + 1) * 132 + c] = to_tf32(v.y);
            Qt[(t4 + 2) * 132 + c] = to_tf32(v.z); Qt[(t4 + 3) * 132 + c] = to_tf32(v.w);
        }
    }

    FragC acc2[2];
    wmma::fill_fragment(acc2[0], 0.f);
    wmma::fill_fragment(acc2[1], 0.f);

    const int myc  = tid >> 1;        // 128 clusters, 2 threads each
    const int half = tid & 1;
    const bool cvalid = (c0 + myc) < NC;
    float tsacc = 0.f;

    for (int ch = 0; ch < 49; ch++) {
        const int tok0 = ch * 64;
        __syncthreads();
        { // load K, V chunk (64x32 each) + w chunk
            const float* kp = g_k + ((size_t)bh * NTOK + tok0) * DH;
            const float* vp = g_v + ((size_t)bh * NTOK + tok0) * DH;
#pragma unroll
            for (int ii = 0; ii < 2; ii++) {
                const int f = tid + ii * 256;
                const int tok = f >> 3, t4 = (f & 7) << 2;
                float4 kv = *(const float4*)(kp + tok * DH + t4);
                Ks[tok * 36 + t4 + 0] = to_tf32(kv.x); Ks[tok * 36 + t4 + 1] = to_tf32(kv.y);
                Ks[tok * 36 + t4 + 2] = to_tf32(kv.z); Ks[tok * 36 + t4 + 3] = to_tf32(kv.w);
                float4 vv = *(const float4*)(vp + tok * DH + t4);
                Vs[tok * 36 + t4 + 0] = to_tf32(vv.x); Vs[tok * 36 + t4 + 1] = to_tf32(vv.y);
                Vs[tok * 36 + t4 + 2] = to_tf32(vv.z); Vs[tok * 36 + t4 + 3] = to_tf32(vv.w);
            }
            if (tid < 64) ws[tid] = g_w[(size_t)bh * NTOK + tok0 + tid];
        }
        __syncthreads();

        // S = K (64x32) x Q^T (32x128)
        FragC accS[2][2];
#pragma unroll
        for (int i = 0; i < 2; i++)
#pragma unroll
            for (int j = 0; j < 2; j++) wmma::fill_fragment(accS[i][j], 0.f);
#pragma unroll
        for (int kk = 0; kk < 32; kk += 8) {
            FragA a[2]; FragB bq[2];
#pragma unroll
            for (int fm = 0; fm < 2; fm++)
                wmma::load_matrix_sync(a[fm], &Ks[(wm * 32 + fm * 16) * 36 + kk], 36);
#pragma unroll
            for (int fn = 0; fn < 2; fn++)
                wmma::load_matrix_sync(bq[fn], &Qt[kk * 132 + wn * 32 + fn * 16], 132);
#pragma unroll
            for (int fm = 0; fm < 2; fm++)
#pragma unroll
                for (int fn = 0; fn < 2; fn++)
                    wmma::mma_sync(accS[fm][fn], a[fm], bq[fn], accS[fm][fn]);
        }
#pragma unroll
        for (int fm = 0; fm < 2; fm++)
#pragma unroll
            for (int fn = 0; fn < 2; fn++)
                wmma::store_matrix_sync(&Ss[(wm * 32 + fm * 16) * 132 + wn * 32 + fn * 16],
                                        accS[fm][fn], 132, wmma::mem_row_major);
        __syncthreads();

        // P = exp(S*scale)*w, stored transposed Pt[c][tok]; ts colsum fused
#pragma unroll
        for (int j = 0; j < 32; j++) {
            const int row = half * 32 + j;
            float p = 0.f;
            if (cvalid) p = __expf(Ss[row * 132 + myc] * SCALE) * ws[row];
            Pt[myc * 68 + row] = to_tf32(p);
            tsacc += p;
        }
        __syncthreads();

        // c2 += P^T (128x64) x V (64x32); warp covers 16 cluster rows
#pragma unroll
        for (int kk = 0; kk < 64; kk += 8) {
            FragA a;
            wmma::load_matrix_sync(a, &Pt[(warp * 16) * 68 + kk], 68);
            FragB bv[2];
            wmma::load_matrix_sync(bv[0], &Vs[kk * 36 + 0], 36);
            wmma::load_matrix_sync(bv[1], &Vs[kk * 36 + 16], 36);
            wmma::mma_sync(acc2[0], a, bv[0], acc2[0]);
            wmma::mma_sync(acc2[1], a, bv[1], acc2[1]);
        }
    }

    // combine ts halves
    tsacc += __shfl_xor_sync(0xffffffffu, tsacc, 1);
    if (half == 0) ts_s[myc] = tsacc;
    __syncthreads();

    wmma::store_matrix_sync(&Cs[(warp * 16) * 36 + 0],  acc2[0], 36, wmma::mem_row_major);
    wmma::store_matrix_sync(&Cs[(warp * 16) * 36 + 16], acc2[1], 36, wmma::mem_row_major);
    __syncthreads();

#pragma unroll
    for (int j = 0; j < 16; j++) {
        const int e = tid + j * 256;
        const int c = e >> 5, dh = e & 31;
        const int gc = c0 + c;
        if (gc >= NC) continue;
        const float tsv = ts_s[c];
        g_c2[((size_t)b * NC + gc) * DD + h * DH + dh] =
            Cs[c * 36 + dh] * __fdividef(1.f, tsv + 1e-6f);
        if (dh == 0) g_ts[(size_t)bh * NC + gc] = tsv;
    }
}

// ---------------------------------------------------------------------------
// token_sizes: mean over heads, pair-sum -> [b, 784]
// ---------------------------------------------------------------------------
__global__ void ts_kernel(float* __restrict__ outp)
{
    const int idx = blockIdx.x * blockDim.x + threadIdx.x;
    if (idx >= BB * NP) return;
    const int b = idx / NP, pp = idx % NP;
    float s = 0.f;
#pragma unroll
    for (int h = 0; h < NH; h++) {
        const float* t = g_ts + ((size_t)(b * NH + h)) * NC + 2 * pp;
        s += t[0] + t[1];
    }
    outp[idx] = s * (1.0f / NH);
}

// ---------------------------------------------------------------------------
// Launch
// ---------------------------------------------------------------------------
extern "C" void kernel_launch(void* const* d_in, const int* in_sizes, int n_in,
                              void* d_out, int out_size)
{
    (void)in_sizes; (void)n_in; (void)out_size;
    const float* x         = (const float*)d_in[0];
    const float* clusters  = (const float*)d_in[1];
    const float* g1        = (const float*)d_in[2];
    const float* Wq        = (const float*)d_in[3];
    const float* Wkv       = (const float*)d_in[4];
    const float* Wo        = (const float*)d_in[5];
    const float* res_scale = (const float*)d_in[6];
    const float* g2        = (const float*)d_in[7];
    const float* Wproj     = (const float*)d_in[8];
    float* out = (float*)d_out;

    float *p_xn, *p_cn, *p_q, *p_k, *p_v, *p_c2, *p_y1, *p_yn2;
    cudaGetSymbolAddress((void**)&p_xn,  g_xn);
    cudaGetSymbolAddress((void**)&p_cn,  g_cn);
    cudaGetSymbolAddress((void**)&p_q,   g_q);
    cudaGetSymbolAddress((void**)&p_k,   g_k);
    cudaGetSymbolAddress((void**)&p_v,   g_v);
    cudaGetSymbolAddress((void**)&p_c2,  g_c2);
    cudaGetSymbolAddress((void**)&p_y1,  g_y1);
    cudaGetSymbolAddress((void**)&p_yn2, g_yn2);

    cudaFuncSetAttribute(sgemm_wmma, cudaFuncAttributeMaxDynamicSharedMemorySize, GEMM_SMEM);
    cudaFuncSetAttribute(pass1_wmma, cudaFuncAttributeMaxDynamicSharedMemorySize, P1_SMEM);
    cudaFuncSetAttribute(pass2_wmma, cudaFuncAttributeMaxDynamicSharedMemorySize, P2_SMEM);

    // 1) LayerNorms
    ln_kernel<DD><<<BB * NTOK, 128>>>(x, g1, p_xn);
    ln_kernel<DD><<<BB * NC, 128>>>(clusters, g1, p_cn);

    // 2) Projections (scatter into per-head layouts)
    sgemm_wmma<<<dim3(3, 49), 256, GEMM_SMEM>>>(p_cn, Wq, p_q, nullptr,
                                                BB * NC, DD, DD, 1, nullptr, nullptr);
    sgemm_wmma<<<dim3(6, 98), 256, GEMM_SMEM>>>(p_xn, Wkv, p_k, p_v,
                                                BB * NTOK, 2 * DD, DD, 2, nullptr, nullptr);

    // 3) Softmax stats + fused P^T V
    pass1_wmma<<<dim3(49, BH), 256, P1_SMEM>>>();
    pass2_wmma<<<dim3(13, BH), 256, P2_SMEM>>>();

    // 4) Wo + residual
    sgemm_wmma<<<dim3(3, 49), 256, GEMM_SMEM>>>(p_c2, Wo, p_y1, nullptr,
                                                BB * NC, DD, DD, 3, clusters, res_scale);

    // 5) LN2 + final projection straight into d_out
    ln_kernel<D2><<<BB * NP, 128>>>(p_y1, g2, p_yn2);
    sgemm_wmma<<<dim3(6, 25), 256, GEMM_SMEM>>>(p_yn2, Wproj, out, nullptr,
                                                BB * NP, D2, D2, 0, nullptr, nullptr);

    // 6) token_sizes tail
    ts_kernel<<<(BB * NP + 255) / 256, 256>>>(out + Y_ELEMS);
}

// round 7
// speedup vs baseline: 1.4419x; 1.1631x over previous
#include <cuda_runtime.h>
#include <cuda_fp16.h>
#include <mma.h>
#include <math.h>
#include <cstdint>

using namespace nvcuda;

// ---------------------------------------------------------------------------
// Problem constants
// ---------------------------------------------------------------------------
#define BB 4
#define NTOK 3136          // 56*56
#define NC 1568            // 2*28*28
#define DD 384
#define NH 12
#define DH 32
#define BH (BB*NH)         // 48
#define D2 768
#define NP 784
#define SCALE 0.17677669529663687f
#define Y_ELEMS (BB*NP*D2)

typedef wmma::fragment<wmma::matrix_a, 16, 16, 8, wmma::precision::tf32, wmma::row_major> FragA;
typedef wmma::fragment<wmma::matrix_b, 16, 16, 8, wmma::precision::tf32, wmma::row_major> FragB;
typedef wmma::fragment<wmma::accumulator, 16, 16, 8, float> FragC;

__device__ __forceinline__ float to_tf32(float x) { return wmma::__float_to_tf32(x); }

__device__ __forceinline__ void cp16(void* s, const void* g, bool pred) {
    unsigned int sa = (unsigned int)__cvta_generic_to_shared(s);
    int sz = pred ? 16 : 0;
    asm volatile("cp.async.cg.shared.global [%0], [%1], 16, %2;\n"
                 :: "r"(sa), "l"(g), "r"(sz));
}
__device__ __forceinline__ void cp_commit() { asm volatile("cp.async.commit_group;\n"); }
template<int N> __device__ __forceinline__ void cp_wait() {
    asm volatile("cp.async.wait_group %0;\n" :: "n"(N));
}

// ---------------------------------------------------------------------------
// Scratch
// ---------------------------------------------------------------------------
__device__ float g_xn [BB*NTOK*DD];
__device__ float g_cn [BB*NC*DD];
__device__ float g_qt [BH*DH*NC];        // Q transposed per head: [bh][dh][c]
__device__ float g_k  [BH*NTOK*DH];
__device__ float g_v  [BH*NTOK*DH];
__device__ float g_w  [BH*NTOK];         // exp(-m)/z per (b,h,token)
__device__ __half g_s [(size_t)BH*NC*NTOK];  // S^T * scale, fp16 (472MB)
__device__ float g_c2 [BB*NC*DD];
__device__ float g_ts [BH*NC];
__device__ float g_y1 [BB*NC*DD];
__device__ float g_yn2[BB*NP*D2];
__device__ float g_wq [DD*DD];
__device__ float g_wkv[DD*2*DD];
__device__ float g_wo [DD*DD];
__device__ float g_wpj[D2*D2];

// ---------------------------------------------------------------------------
// tf32 pre-rounding for weights
// ---------------------------------------------------------------------------
__global__ void round4_kernel(const float4* __restrict__ in, float4* __restrict__ outp, int n4)
{
    int i = blockIdx.x * 256 + threadIdx.x;
    if (i < n4) {
        float4 v = in[i];
        v.x = to_tf32(v.x); v.y = to_tf32(v.y);
        v.z = to_tf32(v.z); v.w = to_tf32(v.w);
        outp[i] = v;
    }
}

// ---------------------------------------------------------------------------
// LayerNorm (output rounded to tf32 — it always feeds a wmma A operand)
// ---------------------------------------------------------------------------
template<int D>
__global__ void ln_kernel(const float* __restrict__ in, const float* __restrict__ gamma,
                          float* __restrict__ out)
{
    constexpr int PT = D / 128;
    __shared__ float red[4];
    const int row = blockIdx.x;
    const int tid = threadIdx.x;
    const float* p = in + (size_t)row * D;

    float v[PT];
#pragma unroll
    for (int i = 0; i < PT; i++) v[i] = p[tid + i * 128];

    float s = 0.f;
#pragma unroll
    for (int i = 0; i < PT; i++) s += v[i];
#pragma unroll
    for (int o = 16; o > 0; o >>= 1) s += __shfl_xor_sync(0xffffffffu, s, o);
    if ((tid & 31) == 0) red[tid >> 5] = s;
    __syncthreads();
    const float mu = (red[0] + red[1] + red[2] + red[3]) * (1.0f / D);
    __syncthreads();

    float s2 = 0.f;
#pragma unroll
    for (int i = 0; i < PT; i++) { float dv = v[i] - mu; s2 += dv * dv; }
#pragma unroll
    for (int o = 16; o > 0; o >>= 1) s2 += __shfl_xor_sync(0xffffffffu, s2, o);
    if ((tid & 31) == 0) red[tid >> 5] = s2;
    __syncthreads();
    const float var = (red[0] + red[1] + red[2] + red[3]) * (1.0f / D);
    const float rs = rsqrtf(var + 1e-6f);

    float* po = out + (size_t)row * D;
#pragma unroll
    for (int i = 0; i < PT; i++)
        po[tid + i * 128] = to_tf32((v[i] - mu) * rs * gamma[tid + i * 128]);
}

// ---------------------------------------------------------------------------
// Pipelined TF32 GEMM, 128x128, BK=32, 2-stage cp.async. Inputs pre-rounded.
// mode 0: plain   C0[row*N+col] = acc
// mode 1: g_qt    [((b*NH+h)*DH + t)*NC + c] = tf32(acc)
// mode 2: g_k/g_v [((b*NH+h)*NTOK + nn)*DH + t] = tf32(acc)
// mode 3: C0 = acc + aux1[row,col]*aux2[col]
// ---------------------------------------------------------------------------
#define GSM_STAGE (128*36 + 32*132)            // 8832 floats / stage
#define GEMM_SMEM (2*GSM_STAGE*4)              // 70656 B (Cs 128*132*4=67584 fits)

__device__ __forceinline__ void gemm_issue(float* sm, const float* A, const float* B,
                                           int it, int tid, int brow, int bcol,
                                           int M, int N, int K)
{
    float* As = sm + (it & 1) * GSM_STAGE;
    float* Bs = As + 128 * 36;
    const int k0 = it << 5;
#pragma unroll
    for (int ii = 0; ii < 4; ii++) {
        int g = tid + ii * 256;
        int r = g >> 3, c = (g & 7) << 2;
        int gr = brow + r;
        cp16(&As[r * 36 + c], A + (size_t)gr * K + k0 + c, gr < M);
    }
#pragma unroll
    for (int ii = 0; ii < 4; ii++) {
        int g = tid + ii * 256;
        int r = g >> 5, c = (g & 31) << 2;
        cp16(&Bs[r * 132 + c], B + (size_t)(k0 + r) * N + bcol + c, true);
    }
    cp_commit();
}

__global__ void sgemm_wmma(const float* __restrict__ A, const float* __restrict__ B,
                           float* __restrict__ C0, float* __restrict__ C1,
                           int M, int N, int K, int mode,
                           const float* __restrict__ aux1, const float* __restrict__ aux2)
{
    extern __shared__ float sm[];
    float* Cs = sm;
    const int tid  = threadIdx.x;
    const int warp = tid >> 5;
    const int wm   = warp >> 2;
    const int wn   = warp & 3;
    const int brow = blockIdx.y * 128;
    const int bcol = blockIdx.x * 128;
    const int nIter = K >> 5;

    FragC acc[4][2];
#pragma unroll
    for (int i = 0; i < 4; i++)
#pragma unroll
        for (int j = 0; j < 2; j++) wmma::fill_fragment(acc[i][j], 0.f);

    gemm_issue(sm, A, B, 0, tid, brow, bcol, M, N, K);

    for (int it = 0; it < nIter; it++) {
        if (it + 1 < nIter) {
            gemm_issue(sm, A, B, it + 1, tid, brow, bcol, M, N, K);
            cp_wait<1>();
        } else {
            cp_wait<0>();
        }
        __syncthreads();
        float* As = sm + (it & 1) * GSM_STAGE;
        float* Bs = As + 128 * 36;
#pragma unroll
        for (int kk = 0; kk < 32; kk += 8) {
            FragA a[4]; FragB b[2];
#pragma unroll
            for (int fm = 0; fm < 4; fm++)
                wmma::load_matrix_sync(a[fm], &As[(wm * 64 + fm * 16) * 36 + kk], 36);
#pragma unroll
            for (int fn = 0; fn < 2; fn++)
                wmma::load_matrix_sync(b[fn], &Bs[kk * 132 + wn * 32 + fn * 16], 132);
#pragma unroll
            for (int fm = 0; fm < 4; fm++)
#pragma unroll
                for (int fn = 0; fn < 2; fn++)
                    wmma::mma_sync(acc[fm][fn], a[fm], b[fn], acc[fm][fn]);
        }
        __syncthreads();
    }

    // epilogue via SMEM
#pragma unroll
    for (int fm = 0; fm < 4; fm++)
#pragma unroll
        for (int fn = 0; fn < 2; fn++)
            wmma::store_matrix_sync(&Cs[(wm * 64 + fm * 16) * 132 + wn * 32 + fn * 16],
                                    acc[fm][fn], 132, wmma::mem_row_major);
    __syncthreads();

    if (mode == 1) {
        // row-consecutive mapping so the [..]*NC + c dst is coalesced
#pragma unroll
        for (int j = 0; j < 64; j++) {
            const int e = tid + j * 256;
            const int r = e & 127, c = e >> 7;
            const int row = brow + r, col = bcol + c;
            const int b = row / NC, cc = row % NC;
            const int h = col >> 5, t = col & 31;
            C0[(((size_t)(b * NH + h)) * DH + t) * NC + cc] = to_tf32(Cs[r * 132 + c]);
        }
    } else {
#pragma unroll
        for (int j = 0; j < 64; j++) {
            const int e = tid + j * 256;
            const int r = e >> 7, c = e & 127;
            const int row = brow + r, col = bcol + c;
            if (row >= M) continue;
            const float v = Cs[r * 132 + c];
            if (mode == 0) {
                C0[(size_t)row * N + col] = v;
            } else if (mode == 2) {
                const int b = row / NTOK, nn = row % NTOK;
                const int kvi = col / DD, rr = col % DD;
                const int h = rr >> 5, t = rr & 31;
                float* dst = kvi ? C1 : C0;
                dst[(((size_t)(b * NH + h)) * NTOK + nn) * DH + t] = to_tf32(v);
            } else { // mode 3
                C0[(size_t)row * N + col] = v + aux1[(size_t)row * N + col] * aux2[col];
            }
        }
    }
}

// ---------------------------------------------------------------------------
// Pass 1: per (b,h,tok-tile 64): S = K·Qᵀ over 13 cluster chunks of 128.
// Writes S^T*scale (fp16) to g_s and softmax stats w = exp(-m)/z to g_w.
// 2-stage cp.async on the Q chunks.
// ---------------------------------------------------------------------------
#define P1_QSTAGE (32*132)
#define P1_SMEM ((64*36 + 2*P1_QSTAGE + 64*132)*4)   // 76800 B

__device__ __forceinline__ void p1_issueQ(float* Qt0, const float* qtp, int cc, int tid)
{
    float* Qt = Qt0 + (cc & 1) * P1_QSTAGE;
    const int c0 = cc * 128;
#pragma unroll
    for (int ii = 0; ii < 4; ii++) {
        int g = tid + ii * 256;
        int t = g >> 5, c = (g & 31) << 2;
        cp16(&Qt[t * 132 + c], qtp + (size_t)t * NC + c0 + c, (c0 + c) < NC);
    }
    cp_commit();
}

__global__ void pass1_kernel()
{
    extern __shared__ float sm[];
    float* Ks  = sm;                     // [64][36]
    float* Qt0 = Ks + 64 * 36;           // 2 stages [32][132]
    float* Ss  = Qt0 + 2 * P1_QSTAGE;    // [64][132]

    const int bh   = blockIdx.y;
    const int tok0 = blockIdx.x * 64;
    const int tid  = threadIdx.x;
    const int warp = tid >> 5;
    const int wm   = warp >> 2;
    const int wn   = warp & 3;

    const float* kp  = g_k  + ((size_t)bh * NTOK + tok0) * DH;
    const float* qtp = g_qt + (size_t)bh * DH * NC;

    // K tile + Q stage 0 in group 0
#pragma unroll
    for (int ii = 0; ii < 2; ii++) {
        int g = tid + ii * 256;
        int r = g >> 3, c = (g & 7) << 2;
        cp16(&Ks[r * 36 + c], kp + r * DH + c, true);
    }
    p1_issueQ(Qt0, qtp, 0, tid);

    const int myTok = tid >> 2;
    const int q     = tid & 3;
    float m = -INFINITY, z = 0.f;

    const int cWr   = tid >> 1;    // 0..127: cluster row for S^T write
    const int halfW = tid & 1;

    for (int cc = 0; cc < 13; cc++) {
        if (cc + 1 < 13) { p1_issueQ(Qt0, qtp, cc + 1, tid); cp_wait<1>(); }
        else             { cp_wait<0>(); }
        __syncthreads();
        float* Qt = Qt0 + (cc & 1) * P1_QSTAGE;

        FragC accS[2][2];
#pragma unroll
        for (int i = 0; i < 2; i++)
#pragma unroll
            for (int j = 0; j < 2; j++) wmma::fill_fragment(accS[i][j], 0.f);
#pragma unroll
        for (int kk = 0; kk < 32; kk += 8) {
            FragA a[2]; FragB b[2];
#pragma unroll
            for (int fm = 0; fm < 2; fm++)
                wmma::load_matrix_sync(a[fm], &Ks[(wm * 32 + fm * 16) * 36 + kk], 36);
#pragma unroll
            for (int fn = 0; fn < 2; fn++)
                wmma::load_matrix_sync(b[fn], &Qt[kk * 132 + wn * 32 + fn * 16], 132);
#pragma unroll
            for (int fm = 0; fm < 2; fm++)
#pragma unroll
                for (int fn = 0; fn < 2; fn++)
                    wmma::mma_sync(accS[fm][fn], a[fm], b[fn], accS[fm][fn]);
        }
#pragma unroll
        for (int fm = 0; fm < 2; fm++)
#pragma unroll
            for (int fn = 0; fn < 2; fn++)
                wmma::store_matrix_sync(&Ss[(wm * 32 + fm * 16) * 132 + wn * 32 + fn * 16],
                                        accS[fm][fn], 132, wmma::mem_row_major);
        __syncthreads();

        const int c0 = cc * 128;

        // online stats (4 threads per token, 32 clusters each)
        {
            float lm = -INFINITY;
#pragma unroll
            for (int j = 0; j < 32; j++) {
                const int col = q * 32 + j;
                if (c0 + col < NC) lm = fmaxf(lm, Ss[myTok * 132 + col] * SCALE);
            }
            lm = fmaxf(lm, __shfl_xor_sync(0xffffffffu, lm, 1));
            lm = fmaxf(lm, __shfl_xor_sync(0xffffffffu, lm, 2));
            const float nm = fmaxf(m, lm);
            float se = 0.f;
#pragma unroll
            for (int j = 0; j < 32; j++) {
                const int col = q * 32 + j;
                if (c0 + col < NC) se += __expf(Ss[myTok * 132 + col] * SCALE - nm);
            }
            se += __shfl_xor_sync(0xffffffffu, se, 1);
            se += __shfl_xor_sync(0xffffffffu, se, 2);
            z = z * __expf(m - nm) + se;
            m = nm;
        }

        // write S^T * scale (fp16): row c (64 contiguous tokens), 32 per thread
        if (c0 + cWr < NC) {
            __half hb[32];
#pragma unroll
            for (int j = 0; j < 32; j++)
                hb[j] = __float2half_rn(Ss[(halfW * 32 + j) * 132 + cWr] * SCALE);
            uint4* dst = (uint4*)(g_s + ((size_t)bh * NC + c0 + cWr) * NTOK + tok0 + halfW * 32);
            const uint4* src = (const uint4*)hb;
            dst[0] = src[0]; dst[1] = src[1]; dst[2] = src[2]; dst[3] = src[3];
        }
    }

    if (q == 0)
        g_w[(size_t)bh * NTOK + tok0 + myTok] = __fdividef(__expf(-m), z);
}

// ---------------------------------------------------------------------------
// Pass 2: per (b,h,c-tile 128): stream S^T chunks, P = exp(s)·w, c2 += PᵀV.
// 2-stage cp.async on S^T/V/w chunks of 64 tokens, 49 chunks.
// ---------------------------------------------------------------------------
#define P2_SH_OFF   0                              // __half [2][128][72]
#define P2_VS_OFF   (2*128*72*2)                   // 36864: float [2][64][36]
#define P2_WS_OFF   (P2_VS_OFF + 2*64*36*4)        // 55296: float [2][64]
#define P2_PT_OFF   (P2_WS_OFF + 2*64*4)           // 55808: float [128][68]
#define P2_TS_OFF   (P2_PT_OFF + 128*68*4)         // 90624: float [128]
#define P2_SMEM     (P2_TS_OFF + 128*4)            // 91136 B

__device__ __forceinline__ void p2_issue(char* smc, int bh, int c0, int ch, int tid)
{
    const int tok0 = ch * 64;
    __half* Sh = (__half*)(smc + P2_SH_OFF) + (ch & 1) * 128 * 72;
    float*  Vs = (float*)(smc + P2_VS_OFF) + (ch & 1) * 64 * 36;
    float*  ws = (float*)(smc + P2_WS_OFF) + (ch & 1) * 64;
    const __half* sp = g_s + (size_t)(bh * NC + c0) * NTOK + tok0;
    const float*  vp = g_v + ((size_t)bh * NTOK + tok0) * DH;
#pragma unroll
    for (int ii = 0; ii < 4; ii++) {
        int g = tid + ii * 256;
        int c = g >> 3, tk = (g & 7) << 3;
        cp16(&Sh[c * 72 + tk], sp + (size_t)c * NTOK + tk, (c0 + c) < NC);
    }
#pragma unroll
    for (int ii = 0; ii < 2; ii++) {
        int g = tid + ii * 256;
        int r = g >> 3, c = (g & 7) << 2;
        cp16(&Vs[r * 36 + c], vp + r * DH + c, true);
    }
    if (tid < 16)
        cp16(&ws[tid * 4], g_w + (size_t)bh * NTOK + tok0 + tid * 4, true);
    cp_commit();
}

__global__ void pass2_kernel()
{
    extern __shared__ char smc[];
    float* Pt   = (float*)(smc + P2_PT_OFF);   // [128][68]
    float* ts_s = (float*)(smc + P2_TS_OFF);   // [128]
    float* Cs   = Pt;                          // epilogue alias [128][36]

    const int bh = blockIdx.y;
    const int b  = bh / NH, h = bh % NH;
    const int c0 = blockIdx.x * 128;
    const int tid  = threadIdx.x;
    const int warp = tid >> 5;

    const int myc  = tid >> 1;
    const int half = tid & 1;
    const bool cvalid = (c0 + myc) < NC;

    FragC acc2[2];
    wmma::fill_fragment(acc2[0], 0.f);
    wmma::fill_fragment(acc2[1], 0.f);
    float tsacc = 0.f;

    p2_issue(smc, bh, c0, 0, tid);

    for (int ch = 0; ch < 49; ch++) {
        cp_wait<0>();
        __syncthreads();
        if (ch + 1 < 49) p2_issue(smc, bh, c0, ch + 1, tid);

        const __half* Sh = (const __half*)(smc + P2_SH_OFF) + (ch & 1) * 128 * 72;
        const float*  Vs = (const float*)(smc + P2_VS_OFF) + (ch & 1) * 64 * 36;
        const float*  ws = (const float*)(smc + P2_WS_OFF) + (ch & 1) * 64;

        // P row (cluster myc), 32 tokens per thread
        if (cvalid) {
#pragma unroll
            for (int j = 0; j < 32; j++) {
                const int tok = half * 32 + j;
                float p = __expf(__half2float(Sh[myc * 72 + tok])) * ws[tok];
                Pt[myc * 68 + tok] = to_tf32(p);
                tsacc += p;
            }
        } else {
#pragma unroll
            for (int j = 0; j < 32; j++)
                Pt[myc * 68 + half * 32 + j] = 0.f;
        }
        __syncthreads();

        // c2 += P (128x64) x V (64x32); warp covers 16 cluster rows
#pragma unroll
        for (int kk = 0; kk < 64; kk += 8) {
            FragA a;
            wmma::load_matrix_sync(a, &Pt[(warp * 16) * 68 + kk], 68);
            FragB bv[2];
            wmma::load_matrix_sync(bv[0], &Vs[kk * 36 + 0], 36);
            wmma::load_matrix_sync(bv[1], &Vs[kk * 36 + 16], 36);
            wmma::mma_sync(acc2[0], a, bv[0], acc2[0]);
            wmma::mma_sync(acc2[1], a, bv[1], acc2[1]);
        }
    }

    tsacc += __shfl_xor_sync(0xffffffffu, tsacc, 1);
    __syncthreads();
    if (half == 0) ts_s[myc] = tsacc;
    __syncthreads();   // also guards Cs alias of Pt

    wmma::store_matrix_sync(&Cs[(warp * 16) * 36 + 0],  acc2[0], 36, wmma::mem_row_major);
    wmma::store_matrix_sync(&Cs[(warp * 16) * 36 + 16], acc2[1], 36, wmma::mem_row_major);
    __syncthreads();

#pragma unroll
    for (int j = 0; j < 16; j++) {
        const int e = tid + j * 256;
        const int c = e >> 5, dh = e & 31;
        const int gc = c0 + c;
        if (gc >= NC) continue;
        const float tsv = ts_s[c];
        g_c2[((size_t)b * NC + gc) * DD + h * DH + dh] =
            to_tf32(Cs[c * 36 + dh] * __fdividef(1.f, tsv + 1e-6f));
        if (dh == 0) g_ts[(size_t)bh * NC + gc] = tsv;
    }
}

// ---------------------------------------------------------------------------
// token_sizes tail
// ---------------------------------------------------------------------------
__global__ void ts_kernel(float* __restrict__ outp)
{
    const int idx = blockIdx.x * blockDim.x + threadIdx.x;
    if (idx >= BB * NP) return;
    const int b = idx / NP, pp = idx % NP;
    float s = 0.f;
#pragma unroll
    for (int h = 0; h < NH; h++) {
        const float* t = g_ts + ((size_t)(b * NH + h)) * NC + 2 * pp;
        s += t[0] + t[1];
    }
    outp[idx] = s * (1.0f / NH);
}

// ---------------------------------------------------------------------------
// Launch
// ---------------------------------------------------------------------------
extern "C" void kernel_launch(void* const* d_in, const int* in_sizes, int n_in,
                              void* d_out, int out_size)
{
    (void)in_sizes; (void)n_in; (void)out_size;
    const float* x         = (const float*)d_in[0];
    const float* clusters  = (const float*)d_in[1];
    const float* g1        = (const float*)d_in[2];
    const float* Wq        = (const float*)d_in[3];
    const float* Wkv       = (const float*)d_in[4];
    const float* Wo        = (const float*)d_in[5];
    const float* res_scale = (const float*)d_in[6];
    const float* g2        = (const float*)d_in[7];
    const float* Wproj     = (const float*)d_in[8];
    float* out = (float*)d_out;

    float *p_xn, *p_cn, *p_qt, *p_k, *p_v, *p_c2, *p_y1, *p_yn2;
    float *p_wq, *p_wkv, *p_wo, *p_wpj;
    cudaGetSymbolAddress((void**)&p_xn,  g_xn);
    cudaGetSymbolAddress((void**)&p_cn,  g_cn);
    cudaGetSymbolAddress((void**)&p_qt,  g_qt);
    cudaGetSymbolAddress((void**)&p_k,   g_k);
    cudaGetSymbolAddress((void**)&p_v,   g_v);
    cudaGetSymbolAddress((void**)&p_c2,  g_c2);
    cudaGetSymbolAddress((void**)&p_y1,  g_y1);
    cudaGetSymbolAddress((void**)&p_yn2, g_yn2);
    cudaGetSymbolAddress((void**)&p_wq,  g_wq);
    cudaGetSymbolAddress((void**)&p_wkv, g_wkv);
    cudaGetSymbolAddress((void**)&p_wo,  g_wo);
    cudaGetSymbolAddress((void**)&p_wpj, g_wpj);

    cudaFuncSetAttribute(sgemm_wmma,   cudaFuncAttributeMaxDynamicSharedMemorySize, GEMM_SMEM);
    cudaFuncSetAttribute(pass1_kernel, cudaFuncAttributeMaxDynamicSharedMemorySize, P1_SMEM);
    cudaFuncSetAttribute(pass2_kernel, cudaFuncAttributeMaxDynamicSharedMemorySize, P2_SMEM);

    // 0) pre-round weights to tf32
    round4_kernel<<<(DD*DD/4 + 255)/256, 256>>>((const float4*)Wq,    (float4*)p_wq,  DD*DD/4);
    round4_kernel<<<(DD*2*DD/4 + 255)/256, 256>>>((const float4*)Wkv, (float4*)p_wkv, DD*2*DD/4);
    round4_kernel<<<(DD*DD/4 + 255)/256, 256>>>((const float4*)Wo,    (float4*)p_wo,  DD*DD/4);
    round4_kernel<<<(D2*D2/4 + 255)/256, 256>>>((const float4*)Wproj, (float4*)p_wpj, D2*D2/4);

    // 1) LayerNorms
    ln_kernel<DD><<<BB * NTOK, 128>>>(x, g1, p_xn);
    ln_kernel<DD><<<BB * NC, 128>>>(clusters, g1, p_cn);

    // 2) Projections (scatter into per-head layouts)
    sgemm_wmma<<<dim3(3, 49), 256, GEMM_SMEM>>>(p_cn, p_wq, p_qt, nullptr,
                                                BB * NC, DD, DD, 1, nullptr, nullptr);
    sgemm_wmma<<<dim3(6, 98), 256, GEMM_SMEM>>>(p_xn, p_wkv, p_k, p_v,
                                                BB * NTOK, 2 * DD, DD, 2, nullptr, nullptr);

    // 3) QK + stats + S store; then P^T V streaming S
    pass1_kernel<<<dim3(49, BH), 256, P1_SMEM>>>();
    pass2_kernel<<<dim3(13, BH), 256, P2_SMEM>>>();

    // 4) Wo + residual
    sgemm_wmma<<<dim3(3, 49), 256, GEMM_SMEM>>>(p_c2, p_wo, p_y1, nullptr,
                                                BB * NC, DD, DD, 3, clusters, res_scale);

    // 5) LN2 + final projection into d_out
    ln_kernel<D2><<<BB * NP, 128>>>(p_y1, g2, p_yn2);
    sgemm_wmma<<<dim3(6, 25), 256, GEMM_SMEM>>>(p_yn2, p_wpj, out, nullptr,
                                                BB * NP, D2, D2, 0, nullptr, nullptr);

    // 6) token_sizes tail
    ts_kernel<<<(BB * NP + 255) / 256, 256>>>(out + Y_ELEMS);
}

// round 8
// speedup vs baseline: 2.2198x; 1.5395x over previous
#include <cuda_runtime.h>
#include <cuda_fp16.h>
#include <mma.h>
#include <math.h>
#include <cstdint>

using namespace nvcuda;

// ---------------------------------------------------------------------------
// Problem constants
// ---------------------------------------------------------------------------
#define BB 4
#define NTOK 3136          // 56*56
#define NC 1568            // 2*28*28
#define DD 384
#define NH 12
#define DH 32
#define BH (BB*NH)         // 48
#define D2 768
#define NP 784
#define SCALE 0.17677669529663687f
#define Y_ELEMS (BB*NP*D2)

typedef wmma::fragment<wmma::matrix_a, 16, 16, 16, __half, wmma::row_major> HFragA;
typedef wmma::fragment<wmma::matrix_b, 16, 16, 16, __half, wmma::row_major> HFragB;
typedef wmma::fragment<wmma::accumulator, 16, 16, 16, float> HFragC;

__device__ __forceinline__ void cp16(void* s, const void* g, bool pred) {
    unsigned int sa = (unsigned int)__cvta_generic_to_shared(s);
    int sz = pred ? 16 : 0;
    asm volatile("cp.async.cg.shared.global [%0], [%1], 16, %2;\n"
                 :: "r"(sa), "l"(g), "r"(sz));
}
__device__ __forceinline__ void cp_commit() { asm volatile("cp.async.commit_group;\n"); }
template<int N> __device__ __forceinline__ void cp_wait() {
    asm volatile("cp.async.wait_group %0;\n" :: "n"(N));
}

// ---------------------------------------------------------------------------
// Scratch (activations in fp16, residual path fp32)
// ---------------------------------------------------------------------------
__device__ __half g_xn [BB*NTOK*DD];
__device__ __half g_cn [BB*NC*DD];
__device__ __half g_qt [BH*DH*NC];       // Q transposed per head: [bh][dh][c]
__device__ __half g_k  [BH*NTOK*DH];
__device__ __half g_v  [BH*NTOK*DH];
__device__ float  g_w  [BH*NTOK];        // exp(-m)/z per (b,h,token)
__device__ __half g_s  [(size_t)BH*NC*NTOK];  // S^T * scale (472MB)
__device__ __half g_c2 [BB*NC*DD];
__device__ float  g_ts [BH*NC];
__device__ float  g_y1 [BB*NC*DD];
__device__ __half g_yn2[BB*NP*D2];
__device__ __half g_wq [DD*DD];
__device__ __half g_wkv[DD*2*DD];
__device__ __half g_wo [DD*DD];
__device__ __half g_wpj[D2*D2];

// ---------------------------------------------------------------------------
// fp32 -> fp16 weight conversion
// ---------------------------------------------------------------------------
__global__ void half_conv_kernel(const float4* __restrict__ in, __half* __restrict__ outp, int n4)
{
    int i = blockIdx.x * 256 + threadIdx.x;
    if (i < n4) {
        float4 v = in[i];
        __half2* o = (__half2*)(outp + i * 4);
        o[0] = __floats2half2_rn(v.x, v.y);
        o[1] = __floats2half2_rn(v.z, v.w);
    }
}

// ---------------------------------------------------------------------------
// LayerNorm: one CTA (128 threads) per row, fp16 output
// ---------------------------------------------------------------------------
template<int D>
__global__ void ln_kernel(const float* __restrict__ in, const float* __restrict__ gamma,
                          __half* __restrict__ out)
{
    constexpr int PT = D / 128;
    __shared__ float red[4];
    const int row = blockIdx.x;
    const int tid = threadIdx.x;
    const float* p = in + (size_t)row * D;

    float v[PT];
#pragma unroll
    for (int i = 0; i < PT; i++) v[i] = p[tid + i * 128];

    float s = 0.f;
#pragma unroll
    for (int i = 0; i < PT; i++) s += v[i];
#pragma unroll
    for (int o = 16; o > 0; o >>= 1) s += __shfl_xor_sync(0xffffffffu, s, o);
    if ((tid & 31) == 0) red[tid >> 5] = s;
    __syncthreads();
    const float mu = (red[0] + red[1] + red[2] + red[3]) * (1.0f / D);
    __syncthreads();

    float s2 = 0.f;
#pragma unroll
    for (int i = 0; i < PT; i++) { float dv = v[i] - mu; s2 += dv * dv; }
#pragma unroll
    for (int o = 16; o > 0; o >>= 1) s2 += __shfl_xor_sync(0xffffffffu, s2, o);
    if ((tid & 31) == 0) red[tid >> 5] = s2;
    __syncthreads();
    const float var = (red[0] + red[1] + red[2] + red[3]) * (1.0f / D);
    const float rs = rsqrtf(var + 1e-6f);

    __half* po = out + (size_t)row * D;
#pragma unroll
    for (int i = 0; i < PT; i++)
        po[tid + i * 128] = __float2half_rn((v[i] - mu) * rs * gamma[tid + i * 128]);
}

// ---------------------------------------------------------------------------
// Pipelined FP16 GEMM, 128x128 tile, BK=32, 2-stage cp.async, fp32 accum.
// mode 0: plain fp32 C0[row*N+col]
// mode 1: g_qt half [((b*NH+h)*DH + t)*NC + c]
// mode 2: g_k/g_v half [((b*NH+h)*NTOK + nn)*DH + t]
// mode 3: fp32 C0 = acc + aux1[row,col]*aux2[col]
// mode 4: half C0[row*N+col]
// ---------------------------------------------------------------------------
#define GA_H 40                            // A row stride (halves)
#define GB_H 136                           // B row stride (halves)
#define GSM_STAGE (128*GA_H + 32*GB_H)     // 9472 halves / stage
#define GEMM_SMEM (128*132*4)              // Cs dominates: 67584 B

__device__ __forceinline__ void gemm_issue(__half* smh, const __half* A, const __half* B,
                                           int it, int tid, int brow, int bcol,
                                           int M, int N, int K)
{
    __half* As = smh + (it & 1) * GSM_STAGE;
    __half* Bs = As + 128 * GA_H;
    const int k0 = it << 5;
#pragma unroll
    for (int ii = 0; ii < 2; ii++) {     // A: 128 x 32 halves
        int g = tid + ii * 256;
        int r = g >> 2, c = (g & 3) << 3;
        int gr = brow + r;
        cp16(&As[r * GA_H + c], A + (size_t)gr * K + k0 + c, gr < M);
    }
#pragma unroll
    for (int ii = 0; ii < 2; ii++) {     // B: 32 x 128 halves
        int g = tid + ii * 256;
        int r = g >> 4, c = (g & 15) << 3;
        cp16(&Bs[r * GB_H + c], B + (size_t)(k0 + r) * N + bcol + c, true);
    }
    cp_commit();
}

__global__ void hgemm_wmma(const __half* __restrict__ A, const __half* __restrict__ B,
                           void* __restrict__ C0v, __half* __restrict__ C1,
                           int M, int N, int K, int mode,
                           const float* __restrict__ aux1, const float* __restrict__ aux2)
{
    extern __shared__ char smraw[];
    __half* smh = (__half*)smraw;
    float*  Cs  = (float*)smraw;
    const int tid  = threadIdx.x;
    const int warp = tid >> 5;
    const int wm   = warp >> 2;
    const int wn   = warp & 3;
    const int brow = blockIdx.y * 128;
    const int bcol = blockIdx.x * 128;
    const int nIter = K >> 5;

    HFragC acc[4][2];
#pragma unroll
    for (int i = 0; i < 4; i++)
#pragma unroll
        for (int j = 0; j < 2; j++) wmma::fill_fragment(acc[i][j], 0.f);

    gemm_issue(smh, A, B, 0, tid, brow, bcol, M, N, K);

    for (int it = 0; it < nIter; it++) {
        if (it + 1 < nIter) {
            gemm_issue(smh, A, B, it + 1, tid, brow, bcol, M, N, K);
            cp_wait<1>();
        } else {
            cp_wait<0>();
        }
        __syncthreads();
        __half* As = smh + (it & 1) * GSM_STAGE;
        __half* Bs = As + 128 * GA_H;
#pragma unroll
        for (int kk = 0; kk < 32; kk += 16) {
            HFragA a[4]; HFragB b[2];
#pragma unroll
            for (int fm = 0; fm < 4; fm++)
                wmma::load_matrix_sync(a[fm], &As[(wm * 64 + fm * 16) * GA_H + kk], GA_H);
#pragma unroll
            for (int fn = 0; fn < 2; fn++)
                wmma::load_matrix_sync(b[fn], &Bs[kk * GB_H + wn * 32 + fn * 16], GB_H);
#pragma unroll
            for (int fm = 0; fm < 4; fm++)
#pragma unroll
                for (int fn = 0; fn < 2; fn++)
                    wmma::mma_sync(acc[fm][fn], a[fm], b[fn], acc[fm][fn]);
        }
        __syncthreads();
    }

    // epilogue via SMEM (fp32 Cs aliases the stages)
#pragma unroll
    for (int fm = 0; fm < 4; fm++)
#pragma unroll
        for (int fn = 0; fn < 2; fn++)
            wmma::store_matrix_sync(&Cs[(wm * 64 + fm * 16) * 132 + wn * 32 + fn * 16],
                                    acc[fm][fn], 132, wmma::mem_row_major);
    __syncthreads();

    if (mode == 1) {
        __half* C0 = (__half*)C0v;
#pragma unroll
        for (int j = 0; j < 64; j++) {
            const int e = tid + j * 256;
            const int r = e & 127, c = e >> 7;
            const int row = brow + r, col = bcol + c;
            const int b = row / NC, cc = row % NC;
            const int h = col >> 5, t = col & 31;
            C0[(((size_t)(b * NH + h)) * DH + t) * NC + cc] = __float2half_rn(Cs[r * 132 + c]);
        }
    } else {
#pragma unroll
        for (int j = 0; j < 64; j++) {
            const int e = tid + j * 256;
            const int r = e >> 7, c = e & 127;
            const int row = brow + r, col = bcol + c;
            if (row >= M) continue;
            const float v = Cs[r * 132 + c];
            if (mode == 0) {
                ((float*)C0v)[(size_t)row * N + col] = v;
            } else if (mode == 2) {
                const int b = row / NTOK, nn = row % NTOK;
                const int kvi = col / DD, rr = col % DD;
                const int h = rr >> 5, t = rr & 31;
                __half* dst = kvi ? C1 : (__half*)C0v;
                dst[(((size_t)(b * NH + h)) * NTOK + nn) * DH + t] = __float2half_rn(v);
            } else if (mode == 3) {
                ((float*)C0v)[(size_t)row * N + col] =
                    v + aux1[(size_t)row * N + col] * aux2[col];
            } else { // mode 4
                ((__half*)C0v)[(size_t)row * N + col] = __float2half_rn(v);
            }
        }
    }
}

// ---------------------------------------------------------------------------
// Pass 1: per (b,h,tok-tile 64): S = K·Qᵀ over 13 cluster chunks of 128.
// Writes S^T*scale (fp16) to g_s and w = exp(-m)/z to g_w.
// ---------------------------------------------------------------------------
#define P1_KS_OFF  0                               // half [64][40]
#define P1_QT_OFF  (64*40*2)                       // 5120: half [2][32][136]
#define P1_SS_OFF  (P1_QT_OFF + 2*32*136*2)        // 22528: float [64][132]
#define P1_SMEM    (P1_SS_OFF + 64*132*4)          // 56320 B

__device__ __forceinline__ void p1_issueQ(char* smc, const __half* qtp, int cc, int tid)
{
    __half* Qt = (__half*)(smc + P1_QT_OFF) + (cc & 1) * 32 * 136;
    const int c0 = cc * 128;
#pragma unroll
    for (int ii = 0; ii < 2; ii++) {
        int g = tid + ii * 256;
        int t = g >> 4, c = (g & 15) << 3;
        cp16(&Qt[t * 136 + c], qtp + (size_t)t * NC + c0 + c, (c0 + c) < NC);
    }
    cp_commit();
}

__global__ void pass1_kernel()
{
    extern __shared__ char smc[];
    __half* Ks = (__half*)(smc + P1_KS_OFF);   // [64][40]
    float*  Ss = (float*)(smc + P1_SS_OFF);    // [64][132]

    const int bh   = blockIdx.y;
    const int tok0 = blockIdx.x * 64;
    const int tid  = threadIdx.x;
    const int warp = tid >> 5;
    const int wm   = warp >> 2;
    const int wn   = warp & 3;

    const __half* kp  = g_k  + ((size_t)bh * NTOK + tok0) * DH;
    const __half* qtp = g_qt + (size_t)bh * DH * NC;

    { // K tile (64x32 halves) + Q stage 0
        int r = tid >> 2, c = (tid & 3) << 3;
        cp16(&Ks[r * 40 + c], kp + r * DH + c, true);
    }
    p1_issueQ(smc, qtp, 0, tid);

    const int myTok = tid >> 2;
    const int q     = tid & 3;
    float m = -INFINITY, z = 0.f;

    const int cWr   = tid >> 1;
    const int halfW = tid & 1;

    for (int cc = 0; cc < 13; cc++) {
        if (cc + 1 < 13) { p1_issueQ(smc, qtp, cc + 1, tid); cp_wait<1>(); }
        else             { cp_wait<0>(); }
        __syncthreads();
        __half* Qt = (__half*)(smc + P1_QT_OFF) + (cc & 1) * 32 * 136;

        HFragC accS[2][2];
#pragma unroll
        for (int i = 0; i < 2; i++)
#pragma unroll
            for (int j = 0; j < 2; j++) wmma::fill_fragment(accS[i][j], 0.f);
#pragma unroll
        for (int kk = 0; kk < 32; kk += 16) {
            HFragA a[2]; HFragB b[2];
#pragma unroll
            for (int fm = 0; fm < 2; fm++)
                wmma::load_matrix_sync(a[fm], &Ks[(wm * 32 + fm * 16) * 40 + kk], 40);
#pragma unroll
            for (int fn = 0; fn < 2; fn++)
                wmma::load_matrix_sync(b[fn], &Qt[kk * 136 + wn * 32 + fn * 16], 136);
#pragma unroll
            for (int fm = 0; fm < 2; fm++)
#pragma unroll
                for (int fn = 0; fn < 2; fn++)
                    wmma::mma_sync(accS[fm][fn], a[fm], b[fn], accS[fm][fn]);
        }
#pragma unroll
        for (int fm = 0; fm < 2; fm++)
#pragma unroll
            for (int fn = 0; fn < 2; fn++)
                wmma::store_matrix_sync(&Ss[(wm * 32 + fm * 16) * 132 + wn * 32 + fn * 16],
                                        accS[fm][fn], 132, wmma::mem_row_major);
        __syncthreads();

        const int c0 = cc * 128;

        // online stats (4 threads per token, 32 clusters each)
        {
            float lm = -INFINITY;
#pragma unroll
            for (int j = 0; j < 32; j++) {
                const int col = q * 32 + j;
                if (c0 + col < NC) lm = fmaxf(lm, Ss[myTok * 132 + col] * SCALE);
            }
            lm = fmaxf(lm, __shfl_xor_sync(0xffffffffu, lm, 1));
            lm = fmaxf(lm, __shfl_xor_sync(0xffffffffu, lm, 2));
            const float nm = fmaxf(m, lm);
            float se = 0.f;
#pragma unroll
            for (int j = 0; j < 32; j++) {
                const int col = q * 32 + j;
                if (c0 + col < NC) se += __expf(Ss[myTok * 132 + col] * SCALE - nm);
            }
            se += __shfl_xor_sync(0xffffffffu, se, 1);
            se += __shfl_xor_sync(0xffffffffu, se, 2);
            z = z * __expf(m - nm) + se;
            m = nm;
        }

        // write S^T * scale (fp16): row c (64 contiguous tokens), 32 per thread
        if (c0 + cWr < NC) {
            __half hb[32];
#pragma unroll
            for (int j = 0; j < 32; j++)
                hb[j] = __float2half_rn(Ss[(halfW * 32 + j) * 132 + cWr] * SCALE);
            uint4* dst = (uint4*)(g_s + ((size_t)bh * NC + c0 + cWr) * NTOK + tok0 + halfW * 32);
            const uint4* src = (const uint4*)hb;
            dst[0] = src[0]; dst[1] = src[1]; dst[2] = src[2]; dst[3] = src[3];
        }
    }

    if (q == 0)
        g_w[(size_t)bh * NTOK + tok0 + myTok] = __fdividef(__expf(-m), z);
}

// ---------------------------------------------------------------------------
// Pass 2: per (b,h,c-tile 128): stream S^T chunks, P = exp(s)·w (fp16),
// c2 += PᵀV via fp16 wmma; ts = rowsum(P). 2-stage cp.async, 49 chunks.
// ---------------------------------------------------------------------------
#define P2_SH_OFF   0                              // half [2][128][72]
#define P2_VS_OFF   (2*128*72*2)                   // 36864: half [2][64][40]
#define P2_WS_OFF   (P2_VS_OFF + 2*64*40*2)        // 47104: float [2][64]
#define P2_PT_OFF   (P2_WS_OFF + 2*64*4)           // 47616: half [128][72]
#define P2_TS_OFF   (P2_PT_OFF + 128*72*2)         // 66048: float [128]
#define P2_SMEM     (P2_TS_OFF + 128*4)            // 66560 B

__device__ __forceinline__ void p2_issue(char* smc, int bh, int c0, int ch, int tid)
{
    const int tok0 = ch * 64;
    __half* Sh = (__half*)(smc + P2_SH_OFF) + (ch & 1) * 128 * 72;
    __half* Vs = (__half*)(smc + P2_VS_OFF) + (ch & 1) * 64 * 40;
    float*  ws = (float*)(smc + P2_WS_OFF) + (ch & 1) * 64;
    const __half* sp = g_s + (size_t)(bh * NC + c0) * NTOK + tok0;
    const __half* vp = g_v + ((size_t)bh * NTOK + tok0) * DH;
#pragma unroll
    for (int ii = 0; ii < 4; ii++) {
        int g = tid + ii * 256;
        int c = g >> 3, tk = (g & 7) << 3;
        cp16(&Sh[c * 72 + tk], sp + (size_t)c * NTOK + tk, (c0 + c) < NC);
    }
    { // V: 64x32 halves
        int r = tid >> 2, c = (tid & 3) << 3;
        cp16(&Vs[r * 40 + c], vp + r * DH + c, true);
    }
    if (tid < 16)
        cp16(&ws[tid * 4], g_w + (size_t)bh * NTOK + tok0 + tid * 4, true);
    cp_commit();
}

__global__ void pass2_kernel()
{
    extern __shared__ char smc[];
    __half* Pt   = (__half*)(smc + P2_PT_OFF);  // [128][72]
    float*  ts_s = (float*)(smc + P2_TS_OFF);   // [128]
    float*  Cs   = (float*)(smc + P2_PT_OFF);   // epilogue alias [128][36]

    const int bh = blockIdx.y;
    const int b  = bh / NH, h = bh % NH;
    const int c0 = blockIdx.x * 128;
    const int tid  = threadIdx.x;
    const int warp = tid >> 5;

    const int myc  = tid >> 1;
    const int half = tid & 1;
    const bool cvalid = (c0 + myc) < NC;

    HFragC acc2[2];
    wmma::fill_fragment(acc2[0], 0.f);
    wmma::fill_fragment(acc2[1], 0.f);
    float tsacc = 0.f;

    p2_issue(smc, bh, c0, 0, tid);

    for (int ch = 0; ch < 49; ch++) {
        cp_wait<0>();
        __syncthreads();
        if (ch + 1 < 49) p2_issue(smc, bh, c0, ch + 1, tid);

        const __half* Sh = (const __half*)(smc + P2_SH_OFF) + (ch & 1) * 128 * 72;
        const __half* Vs = (const __half*)(smc + P2_VS_OFF) + (ch & 1) * 64 * 40;
        const float*  ws = (const float*)(smc + P2_WS_OFF) + (ch & 1) * 64;

        // P row (cluster myc), 32 tokens per thread
        if (cvalid) {
#pragma unroll
            for (int j = 0; j < 32; j++) {
                const int tok = half * 32 + j;
                float p = __expf(__half2float(Sh[myc * 72 + tok])) * ws[tok];
                Pt[myc * 72 + tok] = __float2half_rn(p);
                tsacc += p;
            }
        } else {
#pragma unroll
            for (int j = 0; j < 32; j++)
                Pt[myc * 72 + half * 32 + j] = __float2half_rn(0.f);
        }
        __syncthreads();

        // c2 += P (128x64) x V (64x32); warp covers 16 cluster rows
#pragma unroll
        for (int kk = 0; kk < 64; kk += 16) {
            HFragA a;
            wmma::load_matrix_sync(a, &Pt[(warp * 16) * 72 + kk], 72);
            HFragB bv[2];
            wmma::load_matrix_sync(bv[0], &Vs[kk * 40 + 0], 40);
            wmma::load_matrix_sync(bv[1], &Vs[kk * 40 + 16], 40);
            wmma::mma_sync(acc2[0], a, bv[0], acc2[0]);
            wmma::mma_sync(acc2[1], a, bv[1], acc2[1]);
        }
        __syncthreads();   // Pt reused next iter
    }

    tsacc += __shfl_xor_sync(0xffffffffu, tsacc, 1);
    if (half == 0) ts_s[myc] = tsacc;
    __syncthreads();

    wmma::store_matrix_sync(&Cs[(warp * 16) * 36 + 0],  acc2[0], 36, wmma::mem_row_major);
    wmma::store_matrix_sync(&Cs[(warp * 16) * 36 + 16], acc2[1], 36, wmma::mem_row_major);
    __syncthreads();

#pragma unroll
    for (int j = 0; j < 16; j++) {
        const int e = tid + j * 256;
        const int c = e >> 5, dh = e & 31;
        const int gc = c0 + c;
        if (gc >= NC) continue;
        const float tsv = ts_s[c];
        g_c2[((size_t)b * NC + gc) * DD + h * DH + dh] =
            __float2half_rn(Cs[c * 36 + dh] * __fdividef(1.f, tsv + 1e-6f));
        if (dh == 0) g_ts[(size_t)bh * NC + gc] = tsv;
    }
}

// ---------------------------------------------------------------------------
// token_sizes tail
// ---------------------------------------------------------------------------
__global__ void ts_kernel(float* __restrict__ outp)
{
    const int idx = blockIdx.x * blockDim.x + threadIdx.x;
    if (idx >= BB * NP) return;
    const int b = idx / NP, pp = idx % NP;
    float s = 0.f;
#pragma unroll
    for (int h = 0; h < NH; h++) {
        const float* t = g_ts + ((size_t)(b * NH + h)) * NC + 2 * pp;
        s += t[0] + t[1];
    }
    outp[idx] = s * (1.0f / NH);
}

// ---------------------------------------------------------------------------
// Launch
// ---------------------------------------------------------------------------
extern "C" void kernel_launch(void* const* d_in, const int* in_sizes, int n_in,
                              void* d_out, int out_size)
{
    (void)in_sizes; (void)n_in; (void)out_size;
    const float* x         = (const float*)d_in[0];
    const float* clusters  = (const float*)d_in[1];
    const float* g1        = (const float*)d_in[2];
    const float* Wq        = (const float*)d_in[3];
    const float* Wkv       = (const float*)d_in[4];
    const float* Wo        = (const float*)d_in[5];
    const float* res_scale = (const float*)d_in[6];
    const float* g2        = (const float*)d_in[7];
    const float* Wproj     = (const float*)d_in[8];
    float* out = (float*)d_out;

    __half *p_xn, *p_cn, *p_qt, *p_k, *p_v, *p_c2, *p_yn2;
    __half *p_wq, *p_wkv, *p_wo, *p_wpj;
    float  *p_y1;
    cudaGetSymbolAddress((void**)&p_xn,  g_xn);
    cudaGetSymbolAddress((void**)&p_cn,  g_cn);
    cudaGetSymbolAddress((void**)&p_qt,  g_qt);
    cudaGetSymbolAddress((void**)&p_k,   g_k);
    cudaGetSymbolAddress((void**)&p_v,   g_v);
    cudaGetSymbolAddress((void**)&p_c2,  g_c2);
    cudaGetSymbolAddress((void**)&p_y1,  g_y1);
    cudaGetSymbolAddress((void**)&p_yn2, g_yn2);
    cudaGetSymbolAddress((void**)&p_wq,  g_wq);
    cudaGetSymbolAddress((void**)&p_wkv, g_wkv);
    cudaGetSymbolAddress((void**)&p_wo,  g_wo);
    cudaGetSymbolAddress((void**)&p_wpj, g_wpj);

    cudaFuncSetAttribute(hgemm_wmma,   cudaFuncAttributeMaxDynamicSharedMemorySize, GEMM_SMEM);
    cudaFuncSetAttribute(pass1_kernel, cudaFuncAttributeMaxDynamicSharedMemorySize, P1_SMEM);
    cudaFuncSetAttribute(pass2_kernel, cudaFuncAttributeMaxDynamicSharedMemorySize, P2_SMEM);

    // 0) convert weights to fp16
    half_conv_kernel<<<(DD*DD/4 + 255)/256, 256>>>((const float4*)Wq,    p_wq,  DD*DD/4);
    half_conv_kernel<<<(DD*2*DD/4 + 255)/256, 256>>>((const float4*)Wkv, p_wkv, DD*2*DD/4);
    half_conv_kernel<<<(DD*DD/4 + 255)/256, 256>>>((const float4*)Wo,    p_wo,  DD*DD/4);
    half_conv_kernel<<<(D2*D2/4 + 255)/256, 256>>>((const float4*)Wproj, p_wpj, D2*D2/4);

    // 1) LayerNorms (fp16 outputs)
    ln_kernel<DD><<<BB * NTOK, 128>>>(x, g1, p_xn);
    ln_kernel<DD><<<BB * NC, 128>>>(clusters, g1, p_cn);

    // 2) Projections (scatter into per-head fp16 layouts)
    hgemm_wmma<<<dim3(3, 49), 256, GEMM_SMEM>>>(p_cn, p_wq, p_qt, nullptr,
                                                BB * NC, DD, DD, 1, nullptr, nullptr);
    hgemm_wmma<<<dim3(6, 98), 256, GEMM_SMEM>>>(p_xn, p_wkv, p_k, p_v,
                                                BB * NTOK, 2 * DD, DD, 2, nullptr, nullptr);

    // 3) QK + stats + S store; then P^T V streaming S
    pass1_kernel<<<dim3(49, BH), 256, P1_SMEM>>>();
    pass2_kernel<<<dim3(13, BH), 256, P2_SMEM>>>();

    // 4) Wo + residual (fp32 out for LN2)
    hgemm_wmma<<<dim3(3, 49), 256, GEMM_SMEM>>>(p_c2, p_wo, p_y1, nullptr,
                                                BB * NC, DD, DD, 3, clusters, res_scale);

    // 5) LN2 (fp16) + final projection into fp32 d_out
    ln_kernel<D2><<<BB * NP, 128>>>(p_y1, g2, p_yn2);
    hgemm_wmma<<<dim3(6, 25), 256, GEMM_SMEM>>>(p_yn2, p_wpj, out, nullptr,
                                                BB * NP, D2, D2, 0, nullptr, nullptr);

    // 6) token_sizes tail
    ts_kernel<<<(BB * NP + 255) / 256, 256>>>(out + Y_ELEMS);
}

// round 11
// speedup vs baseline: 2.5299x; 1.1397x over previous
#include <cuda_runtime.h>
#include <cuda_fp16.h>
#include <mma.h>
#include <math.h>
#include <cstdint>

using namespace nvcuda;

// ---------------------------------------------------------------------------
// Problem constants
// ---------------------------------------------------------------------------
#define BB 4
#define NTOK 3136          // 56*56
#define NC 1568            // 2*28*28
#define NCP 1664           // clusters padded to 13*128
#define DD 384
#define NH 12
#define DH 32
#define BH (BB*NH)         // 48
#define D2 768
#define NP 784
#define SCALE 0.17677669529663687f
#define Y_ELEMS (BB*NP*D2)

typedef wmma::fragment<wmma::matrix_a, 16, 16, 16, __half, wmma::row_major> HFragA;
typedef wmma::fragment<wmma::matrix_a, 16, 16, 16, __half, wmma::col_major> HFragAc;
typedef wmma::fragment<wmma::matrix_b, 16, 16, 16, __half, wmma::row_major> HFragB;
typedef wmma::fragment<wmma::accumulator, 16, 16, 16, float> HFragC;

__device__ __forceinline__ void cp16(void* s, const void* g, bool pred) {
    unsigned int sa = (unsigned int)__cvta_generic_to_shared(s);
    int sz = pred ? 16 : 0;
    asm volatile("cp.async.cg.shared.global [%0], [%1], 16, %2;\n"
                 :: "r"(sa), "l"(g), "r"(sz));
}
__device__ __forceinline__ void cp_commit() { asm volatile("cp.async.commit_group;\n"); }
template<int N> __device__ __forceinline__ void cp_wait() {
    asm volatile("cp.async.wait_group %0;\n" :: "n"(N));
}

// ---------------------------------------------------------------------------
// Scratch
// ---------------------------------------------------------------------------
__device__ __half g_xn [BB*NTOK*DD];
__device__ __half g_cn [BB*NC*DD];
__device__ __half g_qt [BH*DH*NC];       // Q transposed per head: [bh][dh][c]
__device__ __half g_k  [BH*NTOK*DH];
__device__ __half g_v  [BH*NTOK*DH];
__device__ float  g_w  [BH*NTOK];        // 1/z per (b,h,token)
__device__ __half g_e  [(size_t)BH*NTOK*NCP];  // exp(S*scale), [bh][tok][c] (~501MB; pad zero)
__device__ __half g_c2 [BB*NC*DD];
__device__ float  g_ts [BH*NC];
__device__ float  g_y1 [BB*NC*DD];
__device__ __half g_yn2[BB*NP*D2];
__device__ __half g_wq [DD*DD];
__device__ __half g_wkv[DD*2*DD];
__device__ __half g_wo [DD*DD];
__device__ __half g_wpj[D2*D2];

// ---------------------------------------------------------------------------
// fp32 -> fp16 weight conversion
// ---------------------------------------------------------------------------
__global__ void half_conv_kernel(const float4* __restrict__ in, __half* __restrict__ outp, int n4)
{
    int i = blockIdx.x * 256 + threadIdx.x;
    if (i < n4) {
        float4 v = in[i];
        __half2* o = (__half2*)(outp + i * 4);
        o[0] = __floats2half2_rn(v.x, v.y);
        o[1] = __floats2half2_rn(v.z, v.w);
    }
}

// ---------------------------------------------------------------------------
// LayerNorm: one CTA (128 threads) per row, fp16 output
// ---------------------------------------------------------------------------
template<int D>
__global__ void ln_kernel(const float* __restrict__ in, const float* __restrict__ gamma,
                          __half* __restrict__ out)
{
    constexpr int PT = D / 128;
    __shared__ float red[4];
    const int row = blockIdx.x;
    const int tid = threadIdx.x;
    const float* p = in + (size_t)row * D;

    float v[PT];
#pragma unroll
    for (int i = 0; i < PT; i++) v[i] = p[tid + i * 128];

    float s = 0.f;
#pragma unroll
    for (int i = 0; i < PT; i++) s += v[i];
#pragma unroll
    for (int o = 16; o > 0; o >>= 1) s += __shfl_xor_sync(0xffffffffu, s, o);
    if ((tid & 31) == 0) red[tid >> 5] = s;
    __syncthreads();
    const float mu = (red[0] + red[1] + red[2] + red[3]) * (1.0f / D);
    __syncthreads();

    float s2 = 0.f;
#pragma unroll
    for (int i = 0; i < PT; i++) { float dv = v[i] - mu; s2 += dv * dv; }
#pragma unroll
    for (int o = 16; o > 0; o >>= 1) s2 += __shfl_xor_sync(0xffffffffu, s2, o);
    if ((tid & 31) == 0) red[tid >> 5] = s2;
    __syncthreads();
    const float var = (red[0] + red[1] + red[2] + red[3]) * (1.0f / D);
    const float rs = rsqrtf(var + 1e-6f);

    __half* po = out + (size_t)row * D;
#pragma unroll
    for (int i = 0; i < PT; i++)
        po[tid + i * 128] = __float2half_rn((v[i] - mu) * rs * gamma[tid + i * 128]);
}

// ---------------------------------------------------------------------------
// Pipelined FP16 GEMM, 128x128 tile, BK=32, 2-stage cp.async, fp32 accum.
// mode 0: plain fp32 C0 ; mode 1: g_qt half ; mode 2: g_k/g_v half
// mode 3: fp32 C0 = acc + aux1*aux2 ; mode 4: half C0
// ---------------------------------------------------------------------------
#define GA_H 40
#define GB_H 136
#define GSM_STAGE (128*GA_H + 32*GB_H)
#define GEMM_SMEM (128*132*4)

__device__ __forceinline__ void gemm_issue(__half* smh, const __half* A, const __half* B,
                                           int it, int tid, int brow, int bcol,
                                           int M, int N, int K)
{
    __half* As = smh + (it & 1) * GSM_STAGE;
    __half* Bs = As + 128 * GA_H;
    const int k0 = it << 5;
#pragma unroll
    for (int ii = 0; ii < 2; ii++) {
        int g = tid + ii * 256;
        int r = g >> 2, c = (g & 3) << 3;
        int gr = brow + r;
        cp16(&As[r * GA_H + c], A + (size_t)gr * K + k0 + c, gr < M);
    }
#pragma unroll
    for (int ii = 0; ii < 2; ii++) {
        int g = tid + ii * 256;
        int r = g >> 4, c = (g & 15) << 3;
        cp16(&Bs[r * GB_H + c], B + (size_t)(k0 + r) * N + bcol + c, true);
    }
    cp_commit();
}

__global__ void hgemm_wmma(const __half* __restrict__ A, const __half* __restrict__ B,
                           void* __restrict__ C0v, __half* __restrict__ C1,
                           int M, int N, int K, int mode,
                           const float* __restrict__ aux1, const float* __restrict__ aux2)
{
    extern __shared__ char smraw[];
    __half* smh = (__half*)smraw;
    float*  Cs  = (float*)smraw;
    const int tid  = threadIdx.x;
    const int warp = tid >> 5;
    const int wm   = warp >> 2;
    const int wn   = warp & 3;
    const int brow = blockIdx.y * 128;
    const int bcol = blockIdx.x * 128;
    const int nIter = K >> 5;

    HFragC acc[4][2];
#pragma unroll
    for (int i = 0; i < 4; i++)
#pragma unroll
        for (int j = 0; j < 2; j++) wmma::fill_fragment(acc[i][j], 0.f);

    gemm_issue(smh, A, B, 0, tid, brow, bcol, M, N, K);

    for (int it = 0; it < nIter; it++) {
        if (it + 1 < nIter) {
            gemm_issue(smh, A, B, it + 1, tid, brow, bcol, M, N, K);
            cp_wait<1>();
        } else {
            cp_wait<0>();
        }
        __syncthreads();
        __half* As = smh + (it & 1) * GSM_STAGE;
        __half* Bs = As + 128 * GA_H;
#pragma unroll
        for (int kk = 0; kk < 32; kk += 16) {
            HFragA a[4]; HFragB b[2];
#pragma unroll
            for (int fm = 0; fm < 4; fm++)
                wmma::load_matrix_sync(a[fm], &As[(wm * 64 + fm * 16) * GA_H + kk], GA_H);
#pragma unroll
            for (int fn = 0; fn < 2; fn++)
                wmma::load_matrix_sync(b[fn], &Bs[kk * GB_H + wn * 32 + fn * 16], GB_H);
#pragma unroll
            for (int fm = 0; fm < 4; fm++)
#pragma unroll
                for (int fn = 0; fn < 2; fn++)
                    wmma::mma_sync(acc[fm][fn], a[fm], b[fn], acc[fm][fn]);
        }
        __syncthreads();
    }

#pragma unroll
    for (int fm = 0; fm < 4; fm++)
#pragma unroll
        for (int fn = 0; fn < 2; fn++)
            wmma::store_matrix_sync(&Cs[(wm * 64 + fm * 16) * 132 + wn * 32 + fn * 16],
                                    acc[fm][fn], 132, wmma::mem_row_major);
    __syncthreads();

    if (mode == 1) {
        __half* C0 = (__half*)C0v;
#pragma unroll
        for (int j = 0; j < 64; j++) {
            const int e = tid + j * 256;
            const int r = e & 127, c = e >> 7;
            const int row = brow + r, col = bcol + c;
            const int b = row / NC, cc = row % NC;
            const int h = col >> 5, t = col & 31;
            C0[(((size_t)(b * NH + h)) * DH + t) * NC + cc] = __float2half_rn(Cs[r * 132 + c]);
        }
    } else {
#pragma unroll
        for (int j = 0; j < 64; j++) {
            const int e = tid + j * 256;
            const int r = e >> 7, c = e & 127;
            const int row = brow + r, col = bcol + c;
            if (row >= M) continue;
            const float v = Cs[r * 132 + c];
            if (mode == 0) {
                ((float*)C0v)[(size_t)row * N + col] = v;
            } else if (mode == 2) {
                const int b = row / NTOK, nn = row % NTOK;
                const int kvi = col / DD, rr = col % DD;
                const int h = rr >> 5, t = rr & 31;
                __half* dst = kvi ? C1 : (__half*)C0v;
                dst[(((size_t)(b * NH + h)) * NTOK + nn) * DH + t] = __float2half_rn(v);
            } else if (mode == 3) {
                ((float*)C0v)[(size_t)row * N + col] =
                    v + aux1[(size_t)row * N + col] * aux2[col];
            } else {
                ((__half*)C0v)[(size_t)row * N + col] = __float2half_rn(v);
            }
        }
    }
}

// ---------------------------------------------------------------------------
// Pass 1: per (b,h,tok-tile 64): S = K·Qᵀ over 13 cluster chunks of 128.
// Computes e = exp(S*scale) ONCE: accumulates z and writes e (fp16, token-
// major, coalesced) to g_e. w = 1/z (logits bounded, no max needed).
// ---------------------------------------------------------------------------
#define P1_KS_OFF  0                               // half [64][40]
#define P1_QT_OFF  (64*40*2)                       // half [2][32][136]
#define P1_SS_OFF  (P1_QT_OFF + 2*32*136*2)        // float [64][132]
#define P1_SMEM    (P1_SS_OFF + 64*132*4)          // 56320 B

__device__ __forceinline__ void p1_issueQ(char* smc, const __half* qtp, int cc, int tid)
{
    __half* Qt = (__half*)(smc + P1_QT_OFF) + (cc & 1) * 32 * 136;
    const int c0 = cc * 128;
#pragma unroll
    for (int ii = 0; ii < 2; ii++) {
        int g = tid + ii * 256;
        int t = g >> 4, c = (g & 15) << 3;
        cp16(&Qt[t * 136 + c], qtp + (size_t)t * NC + c0 + c, (c0 + c) < NC);
    }
    cp_commit();
}

__global__ void pass1_kernel()
{
    extern __shared__ char smc[];
    __half* Ks = (__half*)(smc + P1_KS_OFF);
    float*  Ss = (float*)(smc + P1_SS_OFF);

    const int bh   = blockIdx.y;
    const int tok0 = blockIdx.x * 64;
    const int tid  = threadIdx.x;
    const int warp = tid >> 5;
    const int wm   = warp >> 2;
    const int wn   = warp & 3;

    const __half* kp  = g_k  + ((size_t)bh * NTOK + tok0) * DH;
    const __half* qtp = g_qt + (size_t)bh * DH * NC;

    { // K tile (64x32 halves) + Q stage 0
        int r = tid >> 2, c = (tid & 3) << 3;
        cp16(&Ks[r * 40 + c], kp + r * DH + c, true);
    }
    p1_issueQ(smc, qtp, 0, tid);

    const int myTok = tid >> 2;
    const int q     = tid & 3;
    float z = 0.f;

    for (int cc = 0; cc < 13; cc++) {
        if (cc + 1 < 13) { p1_issueQ(smc, qtp, cc + 1, tid); cp_wait<1>(); }
        else             { cp_wait<0>(); }
        __syncthreads();
        __half* Qt = (__half*)(smc + P1_QT_OFF) + (cc & 1) * 32 * 136;

        HFragC accS[2][2];
#pragma unroll
        for (int i = 0; i < 2; i++)
#pragma unroll
            for (int j = 0; j < 2; j++) wmma::fill_fragment(accS[i][j], 0.f);
#pragma unroll
        for (int kk = 0; kk < 32; kk += 16) {
            HFragA a[2]; HFragB b[2];
#pragma unroll
            for (int fm = 0; fm < 2; fm++)
                wmma::load_matrix_sync(a[fm], &Ks[(wm * 32 + fm * 16) * 40 + kk], 40);
#pragma unroll
            for (int fn = 0; fn < 2; fn++)
                wmma::load_matrix_sync(b[fn], &Qt[kk * 136 + wn * 32 + fn * 16], 136);
#pragma unroll
            for (int fm = 0; fm < 2; fm++)
#pragma unroll
                for (int fn = 0; fn < 2; fn++)
                    wmma::mma_sync(accS[fm][fn], a[fm], b[fn], accS[fm][fn]);
        }
#pragma unroll
        for (int fm = 0; fm < 2; fm++)
#pragma unroll
            for (int fn = 0; fn < 2; fn++)
                wmma::store_matrix_sync(&Ss[(wm * 32 + fm * 16) * 132 + wn * 32 + fn * 16],
                                        accS[fm][fn], 132, wmma::mem_row_major);
        __syncthreads();

        const int c0 = cc * 128;
        const int cbase = c0 + q * 32;
        if (cbase < NC) {      // NC boundary is 32-aligned within chunks
            __half hb[32];
#pragma unroll
            for (int jj = 0; jj < 32; jj++) {
                const int j = (jj + q * 8) & 31;   // stagger to dodge bank conflicts
                float ev = __expf(Ss[myTok * 132 + q * 32 + j] * SCALE);
                z += ev;
                hb[j] = __float2half_rn(ev);
            }
            uint4* dst = (uint4*)(g_e + ((size_t)bh * NTOK + tok0 + myTok) * NCP + cbase);
            const uint4* src = (const uint4*)hb;
            dst[0] = src[0]; dst[1] = src[1]; dst[2] = src[2]; dst[3] = src[3];
        }
    }

    z += __shfl_xor_sync(0xffffffffu, z, 1);
    z += __shfl_xor_sync(0xffffffffu, z, 2);
    if (q == 0)
        g_w[(size_t)bh * NTOK + tok0 + myTok] = __fdividef(1.f, z);
}

// ---------------------------------------------------------------------------
// Pass 2: per (b,h,c-tile 128): stream e tiles (A col_major, zero per-element
// work), V'' = [w·V | w | 0], one MMA chain gives c2 AND ts (col 32).
// ---------------------------------------------------------------------------
#define P2_EH_OFF   0                              // half [2][64][136]
#define P2_VR_OFF   (2*64*136*2)                   // 34816: half [2][64][40]
#define P2_WZ_OFF   (P2_VR_OFF + 2*64*40*2)        // 45056: float [2][64]
#define P2_VP_OFF   (P2_WZ_OFF + 2*64*4)           // 45568: half [64][56]
#define P2_SMEM     (P2_VP_OFF + 64*56*2)          // 52736 B
// epilogue Cs aliases EH: float [128][52] = 26624 B

__device__ __forceinline__ void p2_issue(char* smc, int bh, int c0, int ch, int tid)
{
    const int tok0 = ch * 64;
    __half* Eh = (__half*)(smc + P2_EH_OFF) + (ch & 1) * 64 * 136;
    __half* Vr = (__half*)(smc + P2_VR_OFF) + (ch & 1) * 64 * 40;
    float*  wz = (float*)(smc + P2_WZ_OFF) + (ch & 1) * 64;
    const __half* ep = g_e + ((size_t)bh * NTOK + tok0) * NCP + c0;
    const __half* vp = g_v + ((size_t)bh * NTOK + tok0) * DH;
#pragma unroll
    for (int ii = 0; ii < 4; ii++) {              // e tile: 64 rows x 128 halves
        int g = tid + ii * 256;
        int r = g >> 4, c = (g & 15) << 3;
        cp16(&Eh[r * 136 + c], ep + (size_t)r * NCP + c, true);
    }
    {                                             // V: 64 x 32 halves
        int r = tid >> 2, c = (tid & 3) << 3;
        cp16(&Vr[r * 40 + c], vp + r * DH + c, true);
    }
    if (tid < 16)
        cp16(&wz[tid * 4], g_w + (size_t)bh * NTOK + tok0 + tid * 4, true);
    cp_commit();
}

__global__ void pass2_kernel()
{
    extern __shared__ char smc[];
    __half* Vp = (__half*)(smc + P2_VP_OFF);   // [64][56]
    float*  Cs = (float*)(smc + P2_EH_OFF);    // epilogue alias [128][52]

    const int bh = blockIdx.y;
    const int b  = bh / NH, h = bh % NH;
    const int c0 = blockIdx.x * 128;
    const int tid  = threadIdx.x;
    const int warp = tid >> 5;

    // zero the constant pad columns of V'' once (33..55)
    if (tid < 64) {
#pragma unroll
        for (int c = 33; c < 56; c++) Vp[tid * 56 + c] = __float2half_rn(0.f);
    }

    HFragC acc[3];
#pragma unroll
    for (int i = 0; i < 3; i++) wmma::fill_fragment(acc[i], 0.f);

    p2_issue(smc, bh, c0, 0, tid);

    for (int ch = 0; ch < 49; ch++) {
        cp_wait<0>();
        __syncthreads();
        if (ch + 1 < 49) p2_issue(smc, bh, c0, ch + 1, tid);

        const __half* Eh = (const __half*)(smc + P2_EH_OFF) + (ch & 1) * 64 * 136;
        const __half* Vr = (const __half*)(smc + P2_VR_OFF) + (ch & 1) * 64 * 40;
        const float*  wz = (const float*)(smc + P2_WZ_OFF) + (ch & 1) * 64;

        // build V'' = [w*V | w] (cols 33+ stay zero)
        {
            const int r = tid >> 2, cg = tid & 3;
            const float wv = wz[r];
            __half hb[8];
#pragma unroll
            for (int k = 0; k < 8; k++)
                hb[k] = __float2half_rn(wv * __half2float(Vr[r * 40 + cg * 8 + k]));
            *(uint4*)&Vp[r * 56 + cg * 8] = *(const uint4*)hb;
            if (cg == 0) Vp[r * 56 + 32] = __float2half_rn(wv);
        }
        __syncthreads();

        // c2[128 c][48] += e(col_major 128x64) x V''(64x48)
#pragma unroll
        for (int kk = 0; kk < 64; kk += 16) {
            HFragAc a;
            wmma::load_matrix_sync(a, &Eh[kk * 136 + warp * 16], 136);
#pragma unroll
            for (int fn = 0; fn < 3; fn++) {
                HFragB bv;
                wmma::load_matrix_sync(bv, &Vp[kk * 56 + fn * 16], 56);
                wmma::mma_sync(acc[fn], a, bv, acc[fn]);
            }
        }
        __syncthreads();   // Eh/Vp reused next iter
    }

#pragma unroll
    for (int fn = 0; fn < 3; fn++)
        wmma::store_matrix_sync(&Cs[(warp * 16) * 52 + fn * 16], acc[fn], 52,
                                wmma::mem_row_major);
    __syncthreads();

#pragma unroll
    for (int j = 0; j < 16; j++) {
        const int e = tid + j * 256;
        const int c = e >> 5, dh = e & 31;
        const int gc = c0 + c;
        if (gc >= NC) continue;
        const float tsv = Cs[c * 52 + 32];
        g_c2[((size_t)b * NC + gc) * DD + h * DH + dh] =
            __float2half_rn(Cs[c * 52 + dh] * __fdividef(1.f, tsv + 1e-6f));
        if (dh == 0) g_ts[(size_t)bh * NC + gc] = tsv;
    }
}

// ---------------------------------------------------------------------------
// token_sizes tail
// ---------------------------------------------------------------------------
__global__ void ts_kernel(float* __restrict__ outp)
{
    const int idx = blockIdx.x * blockDim.x + threadIdx.x;
    if (idx >= BB * NP) return;
    const int b = idx / NP, pp = idx % NP;
    float s = 0.f;
#pragma unroll
    for (int h = 0; h < NH; h++) {
        const float* t = g_ts + ((size_t)(b * NH + h)) * NC + 2 * pp;
        s += t[0] + t[1];
    }
    outp[idx] = s * (1.0f / NH);
}

// ---------------------------------------------------------------------------
// Launch
// ---------------------------------------------------------------------------
extern "C" void kernel_launch(void* const* d_in, const int* in_sizes, int n_in,
                              void* d_out, int out_size)
{
    (void)in_sizes; (void)n_in; (void)out_size;
    const float* x         = (const float*)d_in[0];
    const float* clusters  = (const float*)d_in[1];
    const float* g1        = (const float*)d_in[2];
    const float* Wq        = (const float*)d_in[3];
    const float* Wkv       = (const float*)d_in[4];
    const float* Wo        = (const float*)d_in[5];
    const float* res_scale = (const float*)d_in[6];
    const float* g2        = (const float*)d_in[7];
    const float* Wproj     = (const float*)d_in[8];
    float* out = (float*)d_out;

    __half *p_xn, *p_cn, *p_qt, *p_k, *p_v, *p_c2, *p_yn2;
    __half *p_wq, *p_wkv, *p_wo, *p_wpj;
    float  *p_y1;
    cudaGetSymbolAddress((void**)&p_xn,  g_xn);
    cudaGetSymbolAddress((void**)&p_cn,  g_cn);
    cudaGetSymbolAddress((void**)&p_qt,  g_qt);
    cudaGetSymbolAddress((void**)&p_k,   g_k);
    cudaGetSymbolAddress((void**)&p_v,   g_v);
    cudaGetSymbolAddress((void**)&p_c2,  g_c2);
    cudaGetSymbolAddress((void**)&p_y1,  g_y1);
    cudaGetSymbolAddress((void**)&p_yn2, g_yn2);
    cudaGetSymbolAddress((void**)&p_wq,  g_wq);
    cudaGetSymbolAddress((void**)&p_wkv, g_wkv);
    cudaGetSymbolAddress((void**)&p_wo,  g_wo);
    cudaGetSymbolAddress((void**)&p_wpj, g_wpj);

    cudaFuncSetAttribute(hgemm_wmma,   cudaFuncAttributeMaxDynamicSharedMemorySize, GEMM_SMEM);
    cudaFuncSetAttribute(pass1_kernel, cudaFuncAttributeMaxDynamicSharedMemorySize, P1_SMEM);
    cudaFuncSetAttribute(pass2_kernel, cudaFuncAttributeMaxDynamicSharedMemorySize, P2_SMEM);

    // 0) convert weights to fp16
    half_conv_kernel<<<(DD*DD/4 + 255)/256, 256>>>((const float4*)Wq,    p_wq,  DD*DD/4);
    half_conv_kernel<<<(DD*2*DD/4 + 255)/256, 256>>>((const float4*)Wkv, p_wkv, DD*2*DD/4);
    half_conv_kernel<<<(DD*DD/4 + 255)/256, 256>>>((const float4*)Wo,    p_wo,  DD*DD/4);
    half_conv_kernel<<<(D2*D2/4 + 255)/256, 256>>>((const float4*)Wproj, p_wpj, D2*D2/4);

    // 1) LayerNorms (fp16 outputs)
    ln_kernel<DD><<<BB * NTOK, 128>>>(x, g1, p_xn);
    ln_kernel<DD><<<BB * NC, 128>>>(clusters, g1, p_cn);

    // 2) Projections (scatter into per-head fp16 layouts)
    hgemm_wmma<<<dim3(3, 49), 256, GEMM_SMEM>>>(p_cn, p_wq, p_qt, nullptr,
                                                BB * NC, DD, DD, 1, nullptr, nullptr);
    hgemm_wmma<<<dim3(6, 98), 256, GEMM_SMEM>>>(p_xn, p_wkv, p_k, p_v,
                                                BB * NTOK, 2 * DD, DD, 2, nullptr, nullptr);

    // 3) QK + exp + z (single exp pass); then pure-MMA P^T V streaming e
    pass1_kernel<<<dim3(49, BH), 256, P1_SMEM>>>();
    pass2_kernel<<<dim3(13, BH), 256, P2_SMEM>>>();

    // 4) Wo + residual (fp32 out for LN2)
    hgemm_wmma<<<dim3(3, 49), 256, GEMM_SMEM>>>(p_c2, p_wo, p_y1, nullptr,
                                                BB * NC, DD, DD, 3, clusters, res_scale);

    // 5) LN2 (fp16) + final projection into fp32 d_out
    ln_kernel<D2><<<BB * NP, 128>>>(p_y1, g2, p_yn2);
    hgemm_wmma<<<dim3(6, 25), 256, GEMM_SMEM>>>(p_yn2, p_wpj, out, nullptr,
                                                BB * NP, D2, D2, 0, nullptr, nullptr);

    // 6) token_sizes tail
    ts_kernel<<<(BB * NP + 255) / 256, 256>>>(out + Y_ELEMS);
}

// round 14
// speedup vs baseline: 2.5361x; 1.0025x over previous
#include <cuda_runtime.h>
#include <cuda_fp16.h>
#include <mma.h>
#include <math.h>
#include <cstdint>

using namespace nvcuda;

// ---------------------------------------------------------------------------
// Problem constants
// ---------------------------------------------------------------------------
#define BB 4
#define NTOK 3136          // 56*56
#define NC 1568            // 2*28*28
#define NCP 1664           // clusters padded to 13*128
#define DD 384
#define NH 12
#define DH 32
#define BH (BB*NH)         // 48
#define D2 768
#define NP 784
#define SCALE 0.17677669529663687f
#define Y_ELEMS (BB*NP*D2)

typedef wmma::fragment<wmma::matrix_a, 16, 16, 16, __half, wmma::row_major> HFragA;
typedef wmma::fragment<wmma::matrix_a, 16, 16, 16, __half, wmma::col_major> HFragAc;
typedef wmma::fragment<wmma::matrix_b, 16, 16, 16, __half, wmma::row_major> HFragB;
typedef wmma::fragment<wmma::accumulator, 16, 16, 16, float> HFragC;

__device__ __forceinline__ void cp16(void* s, const void* g, bool pred) {
    unsigned int sa = (unsigned int)__cvta_generic_to_shared(s);
    int sz = pred ? 16 : 0;
    asm volatile("cp.async.cg.shared.global [%0], [%1], 16, %2;\n"
                 :: "r"(sa), "l"(g), "r"(sz));
}
__device__ __forceinline__ void cp_commit() { asm volatile("cp.async.commit_group;\n"); }
template<int N> __device__ __forceinline__ void cp_wait() {
    asm volatile("cp.async.wait_group %0;\n" :: "n"(N));
}

// ---------------------------------------------------------------------------
// Scratch
// ---------------------------------------------------------------------------
__device__ __half g_xn [BB*NTOK*DD];
__device__ __half g_cn [BB*NC*DD];
__device__ __half g_qt [BH*DH*NC];       // Q transposed per head: [bh][dh][c]
__device__ __half g_k  [BH*NTOK*DH];
__device__ __half g_v  [BH*NTOK*DH];
__device__ float  g_w  [BH*NTOK];        // 1/z per (b,h,token)
__device__ __half g_e  [(size_t)BH*NTOK*NCP];  // exp(S*scale), [bh][tok][c] (~501MB; pad zero)
__device__ __half g_c2 [BB*NC*DD];
__device__ float  g_ts [BH*NC];
__device__ float  g_y1 [BB*NC*DD];
__device__ __half g_yn2[BB*NP*D2];
__device__ __half g_wq [DD*DD];
__device__ __half g_wkv[DD*2*DD];
__device__ __half g_wo [DD*DD];
__device__ __half g_wpj[D2*D2];

// ---------------------------------------------------------------------------
// fp32 -> fp16 weight conversion
// ---------------------------------------------------------------------------
__global__ void half_conv_kernel(const float4* __restrict__ in, __half* __restrict__ outp, int n4)
{
    int i = blockIdx.x * 256 + threadIdx.x;
    if (i < n4) {
        float4 v = in[i];
        __half2* o = (__half2*)(outp + i * 4);
        o[0] = __floats2half2_rn(v.x, v.y);
        o[1] = __floats2half2_rn(v.z, v.w);
    }
}

// ---------------------------------------------------------------------------
// LayerNorm: one CTA (128 threads) per row, fp16 output
// ---------------------------------------------------------------------------
template<int D>
__global__ void ln_kernel(const float* __restrict__ in, const float* __restrict__ gamma,
                          __half* __restrict__ out)
{
    constexpr int PT = D / 128;
    __shared__ float red[4];
    const int row = blockIdx.x;
    const int tid = threadIdx.x;
    const float* p = in + (size_t)row * D;

    float v[PT];
#pragma unroll
    for (int i = 0; i < PT; i++) v[i] = p[tid + i * 128];

    float s = 0.f;
#pragma unroll
    for (int i = 0; i < PT; i++) s += v[i];
#pragma unroll
    for (int o = 16; o > 0; o >>= 1) s += __shfl_xor_sync(0xffffffffu, s, o);
    if ((tid & 31) == 0) red[tid >> 5] = s;
    __syncthreads();
    const float mu = (red[0] + red[1] + red[2] + red[3]) * (1.0f / D);
    __syncthreads();

    float s2 = 0.f;
#pragma unroll
    for (int i = 0; i < PT; i++) { float dv = v[i] - mu; s2 += dv * dv; }
#pragma unroll
    for (int o = 16; o > 0; o >>= 1) s2 += __shfl_xor_sync(0xffffffffu, s2, o);
    if ((tid & 31) == 0) red[tid >> 5] = s2;
    __syncthreads();
    const float var = (red[0] + red[1] + red[2] + red[3]) * (1.0f / D);
    const float rs = rsqrtf(var + 1e-6f);

    __half* po = out + (size_t)row * D;
#pragma unroll
    for (int i = 0; i < PT; i++)
        po[tid + i * 128] = __float2half_rn((v[i] - mu) * rs * gamma[tid + i * 128]);
}

// ---------------------------------------------------------------------------
// Pipelined FP16 GEMM, 128x128 tile, BK=32, 2-stage cp.async, fp32 accum.
// mode 0: plain fp32 C0 ; mode 1: g_qt half ; mode 2: g_k/g_v half
// mode 3: fp32 C0 = acc + aux1*aux2 ; mode 4: half C0
// ---------------------------------------------------------------------------
#define GA_H 40
#define GB_H 136
#define GSM_STAGE (128*GA_H + 32*GB_H)
#define GEMM_SMEM (128*132*4)

__device__ __forceinline__ void gemm_issue(__half* smh, const __half* A, const __half* B,
                                           int it, int tid, int brow, int bcol,
                                           int M, int N, int K)
{
    __half* As = smh + (it & 1) * GSM_STAGE;
    __half* Bs = As + 128 * GA_H;
    const int k0 = it << 5;
#pragma unroll
    for (int ii = 0; ii < 2; ii++) {
        int g = tid + ii * 256;
        int r = g >> 2, c = (g & 3) << 3;
        int gr = brow + r;
        cp16(&As[r * GA_H + c], A + (size_t)gr * K + k0 + c, gr < M);
    }
#pragma unroll
    for (int ii = 0; ii < 2; ii++) {
        int g = tid + ii * 256;
        int r = g >> 4, c = (g & 15) << 3;
        cp16(&Bs[r * GB_H + c], B + (size_t)(k0 + r) * N + bcol + c, true);
    }
    cp_commit();
}

__global__ void hgemm_wmma(const __half* __restrict__ A, const __half* __restrict__ B,
                           void* __restrict__ C0v, __half* __restrict__ C1,
                           int M, int N, int K, int mode,
                           const float* __restrict__ aux1, const float* __restrict__ aux2)
{
    extern __shared__ char smraw[];
    __half* smh = (__half*)smraw;
    float*  Cs  = (float*)smraw;
    const int tid  = threadIdx.x;
    const int warp = tid >> 5;
    const int wm   = warp >> 2;
    const int wn   = warp & 3;
    const int brow = blockIdx.y * 128;
    const int bcol = blockIdx.x * 128;
    const int nIter = K >> 5;

    HFragC acc[4][2];
#pragma unroll
    for (int i = 0; i < 4; i++)
#pragma unroll
        for (int j = 0; j < 2; j++) wmma::fill_fragment(acc[i][j], 0.f);

    gemm_issue(smh, A, B, 0, tid, brow, bcol, M, N, K);

    for (int it = 0; it < nIter; it++) {
        if (it + 1 < nIter) {
            gemm_issue(smh, A, B, it + 1, tid, brow, bcol, M, N, K);
            cp_wait<1>();
        } else {
            cp_wait<0>();
        }
        __syncthreads();
        __half* As = smh + (it & 1) * GSM_STAGE;
        __half* Bs = As + 128 * GA_H;
#pragma unroll
        for (int kk = 0; kk < 32; kk += 16) {
            HFragA a[4]; HFragB b[2];
#pragma unroll
            for (int fm = 0; fm < 4; fm++)
                wmma::load_matrix_sync(a[fm], &As[(wm * 64 + fm * 16) * GA_H + kk], GA_H);
#pragma unroll
            for (int fn = 0; fn < 2; fn++)
                wmma::load_matrix_sync(b[fn], &Bs[kk * GB_H + wn * 32 + fn * 16], GB_H);
#pragma unroll
            for (int fm = 0; fm < 4; fm++)
#pragma unroll
                for (int fn = 0; fn < 2; fn++)
                    wmma::mma_sync(acc[fm][fn], a[fm], b[fn], acc[fm][fn]);
        }
        __syncthreads();
    }

#pragma unroll
    for (int fm = 0; fm < 4; fm++)
#pragma unroll
        for (int fn = 0; fn < 2; fn++)
            wmma::store_matrix_sync(&Cs[(wm * 64 + fm * 16) * 132 + wn * 32 + fn * 16],
                                    acc[fm][fn], 132, wmma::mem_row_major);
    __syncthreads();

    if (mode == 1) {
        __half* C0 = (__half*)C0v;
#pragma unroll
        for (int j = 0; j < 64; j++) {
            const int e = tid + j * 256;
            const int r = e & 127, c = e >> 7;
            const int row = brow + r, col = bcol + c;
            const int b = row / NC, cc = row % NC;
            const int h = col >> 5, t = col & 31;
            C0[(((size_t)(b * NH + h)) * DH + t) * NC + cc] = __float2half_rn(Cs[r * 132 + c]);
        }
    } else {
#pragma unroll
        for (int j = 0; j < 64; j++) {
            const int e = tid + j * 256;
            const int r = e >> 7, c = e & 127;
            const int row = brow + r, col = bcol + c;
            if (row >= M) continue;
            const float v = Cs[r * 132 + c];
            if (mode == 0) {
                ((float*)C0v)[(size_t)row * N + col] = v;
            } else if (mode == 2) {
                const int b = row / NTOK, nn = row % NTOK;
                const int kvi = col / DD, rr = col % DD;
                const int h = rr >> 5, t = rr & 31;
                __half* dst = kvi ? C1 : (__half*)C0v;
                dst[(((size_t)(b * NH + h)) * NTOK + nn) * DH + t] = __float2half_rn(v);
            } else if (mode == 3) {
                ((float*)C0v)[(size_t)row * N + col] =
                    v + aux1[(size_t)row * N + col] * aux2[col];
            } else {
                ((__half*)C0v)[(size_t)row * N + col] = __float2half_rn(v);
            }
        }
    }
}

// ---------------------------------------------------------------------------
// Pass 1: per (b,h,tok-tile 64): S = K·Qᵀ over 13 cluster chunks of 128.
// Computes e = exp(S*scale) ONCE: accumulates z and writes e (fp16, token-
// major, coalesced) to g_e. w = 1/z (logits bounded, no max needed).
// ---------------------------------------------------------------------------
#define P1_KS_OFF  0                               // half [64][40]
#define P1_QT_OFF  (64*40*2)                       // half [2][32][136]
#define P1_SS_OFF  (P1_QT_OFF + 2*32*136*2)        // float [64][132]
#define P1_SMEM    (P1_SS_OFF + 64*132*4)          // 56320 B

__device__ __forceinline__ void p1_issueQ(char* smc, const __half* qtp, int cc, int tid)
{
    __half* Qt = (__half*)(smc + P1_QT_OFF) + (cc & 1) * 32 * 136;
    const int c0 = cc * 128;
#pragma unroll
    for (int ii = 0; ii < 2; ii++) {
        int g = tid + ii * 256;
        int t = g >> 4, c = (g & 15) << 3;
        cp16(&Qt[t * 136 + c], qtp + (size_t)t * NC + c0 + c, (c0 + c) < NC);
    }
    cp_commit();
}

__global__ void pass1_kernel()
{
    extern __shared__ char smc[];
    __half* Ks = (__half*)(smc + P1_KS_OFF);
    float*  Ss = (float*)(smc + P1_SS_OFF);

    const int bh   = blockIdx.y;
    const int tok0 = blockIdx.x * 64;
    const int tid  = threadIdx.x;
    const int warp = tid >> 5;
    const int wm   = warp >> 2;
    const int wn   = warp & 3;

    const __half* kp  = g_k  + ((size_t)bh * NTOK + tok0) * DH;
    const __half* qtp = g_qt + (size_t)bh * DH * NC;

    { // K tile (64x32 halves) + Q stage 0
        int r = tid >> 2, c = (tid & 3) << 3;
        cp16(&Ks[r * 40 + c], kp + r * DH + c, true);
    }
    p1_issueQ(smc, qtp, 0, tid);

    const int myTok = tid >> 2;
    const int q     = tid & 3;
    float z = 0.f;

    for (int cc = 0; cc < 13; cc++) {
        if (cc + 1 < 13) { p1_issueQ(smc, qtp, cc + 1, tid); cp_wait<1>(); }
        else             { cp_wait<0>(); }
        __syncthreads();
        __half* Qt = (__half*)(smc + P1_QT_OFF) + (cc & 1) * 32 * 136;

        HFragC accS[2][2];
#pragma unroll
        for (int i = 0; i < 2; i++)
#pragma unroll
            for (int j = 0; j < 2; j++) wmma::fill_fragment(accS[i][j], 0.f);
#pragma unroll
        for (int kk = 0; kk < 32; kk += 16) {
            HFragA a[2]; HFragB b[2];
#pragma unroll
            for (int fm = 0; fm < 2; fm++)
                wmma::load_matrix_sync(a[fm], &Ks[(wm * 32 + fm * 16) * 40 + kk], 40);
#pragma unroll
            for (int fn = 0; fn < 2; fn++)
                wmma::load_matrix_sync(b[fn], &Qt[kk * 136 + wn * 32 + fn * 16], 136);
#pragma unroll
            for (int fm = 0; fm < 2; fm++)
#pragma unroll
                for (int fn = 0; fn < 2; fn++)
                    wmma::mma_sync(accS[fm][fn], a[fm], b[fn], accS[fm][fn]);
        }
#pragma unroll
        for (int fm = 0; fm < 2; fm++)
#pragma unroll
            for (int fn = 0; fn < 2; fn++)
                wmma::store_matrix_sync(&Ss[(wm * 32 + fm * 16) * 132 + wn * 32 + fn * 16],
                                        accS[fm][fn], 132, wmma::mem_row_major);
        __syncthreads();

        const int c0 = cc * 128;
        const int cbase = c0 + q * 32;
        if (cbase < NC) {      // NC boundary is 32-aligned within chunks
            __half hb[32];
#pragma unroll
            for (int jj = 0; jj < 32; jj++) {
                const int j = (jj + q * 8) & 31;   // stagger to dodge bank conflicts
                float ev = __expf(Ss[myTok * 132 + q * 32 + j] * SCALE);
                z += ev;
                hb[j] = __float2half_rn(ev);
            }
            uint4* dst = (uint4*)(g_e + ((size_t)bh * NTOK + tok0 + myTok) * NCP + cbase);
            const uint4* src = (const uint4*)hb;
            dst[0] = src[0]; dst[1] = src[1]; dst[2] = src[2]; dst[3] = src[3];
        }
    }

    z += __shfl_xor_sync(0xffffffffu, z, 1);
    z += __shfl_xor_sync(0xffffffffu, z, 2);
    if (q == 0)
        g_w[(size_t)bh * NTOK + tok0 + myTok] = __fdividef(1.f, z);
}

// ---------------------------------------------------------------------------
// Pass 2: per (b,h,c-tile 128): stream e tiles (A col_major, zero per-element
// work), V'' = [w·V | w | 0], one MMA chain gives c2 AND ts (col 32).
// ---------------------------------------------------------------------------
#define P2_EH_OFF   0                              // half [2][64][136]
#define P2_VR_OFF   (2*64*136*2)                   // 34816: half [2][64][40]
#define P2_WZ_OFF   (P2_VR_OFF + 2*64*40*2)        // 45056: float [2][64]
#define P2_VP_OFF   (P2_WZ_OFF + 2*64*4)           // 45568: half [64][56]
#define P2_SMEM     (P2_VP_OFF + 64*56*2)          // 52736 B
// epilogue Cs aliases EH: float [128][52] = 26624 B

__device__ __forceinline__ void p2_issue(char* smc, int bh, int c0, int ch, int tid)
{
    const int tok0 = ch * 64;
    __half* Eh = (__half*)(smc + P2_EH_OFF) + (ch & 1) * 64 * 136;
    __half* Vr = (__half*)(smc + P2_VR_OFF) + (ch & 1) * 64 * 40;
    float*  wz = (float*)(smc + P2_WZ_OFF) + (ch & 1) * 64;
    const __half* ep = g_e + ((size_t)bh * NTOK + tok0) * NCP + c0;
    const __half* vp = g_v + ((size_t)bh * NTOK + tok0) * DH;
#pragma unroll
    for (int ii = 0; ii < 4; ii++) {              // e tile: 64 rows x 128 halves
        int g = tid + ii * 256;
        int r = g >> 4, c = (g & 15) << 3;
        cp16(&Eh[r * 136 + c], ep + (size_t)r * NCP + c, true);
    }
    {                                             // V: 64 x 32 halves
        int r = tid >> 2, c = (tid & 3) << 3;
        cp16(&Vr[r * 40 + c], vp + r * DH + c, true);
    }
    if (tid < 16)
        cp16(&wz[tid * 4], g_w + (size_t)bh * NTOK + tok0 + tid * 4, true);
    cp_commit();
}

__global__ void pass2_kernel()
{
    extern __shared__ char smc[];
    __half* Vp = (__half*)(smc + P2_VP_OFF);   // [64][56]
    float*  Cs = (float*)(smc + P2_EH_OFF);    // epilogue alias [128][52]

    const int bh = blockIdx.y;
    const int b  = bh / NH, h = bh % NH;
    const int c0 = blockIdx.x * 128;
    const int tid  = threadIdx.x;
    const int warp = tid >> 5;

    // zero the constant pad columns of V'' once (33..55)
    if (tid < 64) {
#pragma unroll
        for (int c = 33; c < 56; c++) Vp[tid * 56 + c] = __float2half_rn(0.f);
    }

    HFragC acc[3];
#pragma unroll
    for (int i = 0; i < 3; i++) wmma::fill_fragment(acc[i], 0.f);

    p2_issue(smc, bh, c0, 0, tid);

    for (int ch = 0; ch < 49; ch++) {
        cp_wait<0>();
        __syncthreads();
        if (ch + 1 < 49) p2_issue(smc, bh, c0, ch + 1, tid);

        const __half* Eh = (const __half*)(smc + P2_EH_OFF) + (ch & 1) * 64 * 136;
        const __half* Vr = (const __half*)(smc + P2_VR_OFF) + (ch & 1) * 64 * 40;
        const float*  wz = (const float*)(smc + P2_WZ_OFF) + (ch & 1) * 64;

        // build V'' = [w*V | w] (cols 33+ stay zero)
        {
            const int r = tid >> 2, cg = tid & 3;
            const float wv = wz[r];
            __half hb[8];
#pragma unroll
            for (int k = 0; k < 8; k++)
                hb[k] = __float2half_rn(wv * __half2float(Vr[r * 40 + cg * 8 + k]));
            *(uint4*)&Vp[r * 56 + cg * 8] = *(const uint4*)hb;
            if (cg == 0) Vp[r * 56 + 32] = __float2half_rn(wv);
        }
        __syncthreads();

        // c2[128 c][48] += e(col_major 128x64) x V''(64x48)
#pragma unroll
        for (int kk = 0; kk < 64; kk += 16) {
            HFragAc a;
            wmma::load_matrix_sync(a, &Eh[kk * 136 + warp * 16], 136);
#pragma unroll
            for (int fn = 0; fn < 3; fn++) {
                HFragB bv;
                wmma::load_matrix_sync(bv, &Vp[kk * 56 + fn * 16], 56);
                wmma::mma_sync(acc[fn], a, bv, acc[fn]);
            }
        }
        __syncthreads();   // Eh/Vp reused next iter
    }

#pragma unroll
    for (int fn = 0; fn < 3; fn++)
        wmma::store_matrix_sync(&Cs[(warp * 16) * 52 + fn * 16], acc[fn], 52,
                                wmma::mem_row_major);
    __syncthreads();

#pragma unroll
    for (int j = 0; j < 16; j++) {
        const int e = tid + j * 256;
        const int c = e >> 5, dh = e & 31;
        const int gc = c0 + c;
        if (gc >= NC) continue;
        const float tsv = Cs[c * 52 + 32];
        g_c2[((size_t)b * NC + gc) * DD + h * DH + dh] =
            __float2half_rn(Cs[c * 52 + dh] * __fdividef(1.f, tsv + 1e-6f));
        if (dh == 0) g_ts[(size_t)bh * NC + gc] = tsv;
    }
}

// ---------------------------------------------------------------------------
// token_sizes tail
// ---------------------------------------------------------------------------
__global__ void ts_kernel(float* __restrict__ outp)
{
    const int idx = blockIdx.x * blockDim.x + threadIdx.x;
    if (idx >= BB * NP) return;
    const int b = idx / NP, pp = idx % NP;
    float s = 0.f;
#pragma unroll
    for (int h = 0; h < NH; h++) {
        const float* t = g_ts + ((size_t)(b * NH + h)) * NC + 2 * pp;
        s += t[0] + t[1];
    }
    outp[idx] = s * (1.0f / NH);
}

// ---------------------------------------------------------------------------
// Launch
// ---------------------------------------------------------------------------
extern "C" void kernel_launch(void* const* d_in, const int* in_sizes, int n_in,
                              void* d_out, int out_size)
{
    (void)in_sizes; (void)n_in; (void)out_size;
    const float* x         = (const float*)d_in[0];
    const float* clusters  = (const float*)d_in[1];
    const float* g1        = (const float*)d_in[2];
    const float* Wq        = (const float*)d_in[3];
    const float* Wkv       = (const float*)d_in[4];
    const float* Wo        = (const float*)d_in[5];
    const float* res_scale = (const float*)d_in[6];
    const float* g2        = (const float*)d_in[7];
    const float* Wproj     = (const float*)d_in[8];
    float* out = (float*)d_out;

    __half *p_xn, *p_cn, *p_qt, *p_k, *p_v, *p_c2, *p_yn2;
    __half *p_wq, *p_wkv, *p_wo, *p_wpj;
    float  *p_y1;
    cudaGetSymbolAddress((void**)&p_xn,  g_xn);
    cudaGetSymbolAddress((void**)&p_cn,  g_cn);
    cudaGetSymbolAddress((void**)&p_qt,  g_qt);
    cudaGetSymbolAddress((void**)&p_k,   g_k);
    cudaGetSymbolAddress((void**)&p_v,   g_v);
    cudaGetSymbolAddress((void**)&p_c2,  g_c2);
    cudaGetSymbolAddress((void**)&p_y1,  g_y1);
    cudaGetSymbolAddress((void**)&p_yn2, g_yn2);
    cudaGetSymbolAddress((void**)&p_wq,  g_wq);
    cudaGetSymbolAddress((void**)&p_wkv, g_wkv);
    cudaGetSymbolAddress((void**)&p_wo,  g_wo);
    cudaGetSymbolAddress((void**)&p_wpj, g_wpj);

    cudaFuncSetAttribute(hgemm_wmma,   cudaFuncAttributeMaxDynamicSharedMemorySize, GEMM_SMEM);
    cudaFuncSetAttribute(pass1_kernel, cudaFuncAttributeMaxDynamicSharedMemorySize, P1_SMEM);
    cudaFuncSetAttribute(pass2_kernel, cudaFuncAttributeMaxDynamicSharedMemorySize, P2_SMEM);

    // 0) convert weights to fp16
    half_conv_kernel<<<(DD*DD/4 + 255)/256, 256>>>((const float4*)Wq,    p_wq,  DD*DD/4);
    half_conv_kernel<<<(DD*2*DD/4 + 255)/256, 256>>>((const float4*)Wkv, p_wkv, DD*2*DD/4);
    half_conv_kernel<<<(DD*DD/4 + 255)/256, 256>>>((const float4*)Wo,    p_wo,  DD*DD/4);
    half_conv_kernel<<<(D2*D2/4 + 255)/256, 256>>>((const float4*)Wproj, p_wpj, D2*D2/4);

    // 1) LayerNorms (fp16 outputs)
    ln_kernel<DD><<<BB * NTOK, 128>>>(x, g1, p_xn);
    ln_kernel<DD><<<BB * NC, 128>>>(clusters, g1, p_cn);

    // 2) Projections (scatter into per-head fp16 layouts)
    hgemm_wmma<<<dim3(3, 49), 256, GEMM_SMEM>>>(p_cn, p_wq, p_qt, nullptr,
                                                BB * NC, DD, DD, 1, nullptr, nullptr);
    hgemm_wmma<<<dim3(6, 98), 256, GEMM_SMEM>>>(p_xn, p_wkv, p_k, p_v,
                                                BB * NTOK, 2 * DD, DD, 2, nullptr, nullptr);

    // 3) QK + exp + z (single exp pass); then pure-MMA P^T V streaming e
    pass1_kernel<<<dim3(49, BH), 256, P1_SMEM>>>();
    pass2_kernel<<<dim3(13, BH), 256, P2_SMEM>>>();

    // 4) Wo + residual (fp32 out for LN2)
    hgemm_wmma<<<dim3(3, 49), 256, GEMM_SMEM>>>(p_c2, p_wo, p_y1, nullptr,
                                                BB * NC, DD, DD, 3, clusters, res_scale);

    // 5) LN2 (fp16) + final projection into fp32 d_out
    ln_kernel<D2><<<BB * NP, 128>>>(p_y1, g2, p_yn2);
    hgemm_wmma<<<dim3(6, 25), 256, GEMM_SMEM>>>(p_yn2, p_wpj, out, nullptr,
                                                BB * NP, D2, D2, 0, nullptr, nullptr);

    // 6) token_sizes tail
    ts_kernel<<<(BB * NP + 255) / 256, 256>>>(out + Y_ELEMS);
}